// round 10
// baseline (speedup 1.0000x reference)
#include <cuda_runtime.h>
#include <math.h>

#define BN 8
#define NP 8192
#define MP 1024
#define KNB 17
#define FS 36

typedef unsigned long long ull;

// ---------------- scratch ----------------
__device__ float g_gvec[BN * 128];
__device__ float g_f2[BN * NP * 128];
__device__ float g_down[BN * MP * 3];
__device__ int   g_knn[BN * MP * KNB];
__device__ float g_csw1t[256 * 256];
__device__ float g_csw2t[256 * 128];
__device__ float g_c1w2t[64 * 128];
__device__ float g_hg[BN * 256];
__device__ ull   g_s2w2d[64 * 64];
__device__ float g_s2w3p[128 * 64];
__device__ float g_w1f[64 * 9];
__device__ float g_b1f[64];
__device__ float g_b2f[64];
__device__ float g_Ap[256 * 256];
__device__ float g_cvec[256];
__device__ float g_vb[256];
__device__ float g_s0[1];

__device__ __forceinline__ ull f2pk(float lo, float hi) {
    ull r; asm("mov.b64 %0,{%1,%2};" : "=l"(r) : "f"(lo), "f"(hi)); return r;
}
__device__ __forceinline__ void f2up(ull v, float& lo, float& hi) {
    asm("mov.b64 {%0,%1},%2;" : "=f"(lo), "=f"(hi) : "l"(v));
}
__device__ __forceinline__ ull addx2(ull a, ull b) {
    ull r; asm("add.rn.f32x2 %0,%1,%2;" : "=l"(r) : "l"(a), "l"(b)); return r;
}
__device__ __forceinline__ ull mulx2(ull a, ull b) {
    ull r; asm("mul.rn.f32x2 %0,%1,%2;" : "=l"(r) : "l"(a), "l"(b)); return r;
}
__device__ __forceinline__ ull fma2(ull a, ull b, ull c) {
    ull r; asm("fma.rn.f32x2 %0,%1,%2,%3;" : "=l"(r) : "l"(a), "l"(b), "l"(c)); return r;
}

// ---------------- prep ----------------------------------------------------
__device__ __forceinline__ void rp_t(const float* __restrict__ w, float* __restrict__ o,
                                     int O, int C, int blk) {
    int g = blk * 256 + threadIdx.x;
    if (g >= O * C) return;
    int c = g / O, oo = g - c * O;
    o[c * O + oo] = w[oo * C + c];
}

__global__ void k_prep(const float* __restrict__ cs_w1, const float* __restrict__ cs_w2,
                       const float* __restrict__ c1_w2,
                       const float* __restrict__ s2_w1, const float* __restrict__ s2_b1,
                       const float* __restrict__ s2_g1, const float* __restrict__ s2_bb1,
                       const float* __restrict__ s2_w2, const float* __restrict__ s2_b2,
                       const float* __restrict__ s2_g2, const float* __restrict__ s2_bb2,
                       const float* __restrict__ s2_w3,
                       const float* __restrict__ q_w, const float* __restrict__ k_w,
                       const float* __restrict__ q_b, const float* __restrict__ k_b,
                       const float* __restrict__ gf,
                       const float* __restrict__ cf_w1, const float* __restrict__ cf_b1,
                       const float* __restrict__ cf_w2, const float* __restrict__ cf_b2) {
    __shared__ float s_buf[512];
    __shared__ float s_h[256];
    __shared__ float s_red[8];
    const float bnc = 1.f / sqrtf(1.0f + 1e-5f);
    int blk = blockIdx.x, t = threadIdx.x;
    if (blk < 256)  { rp_t(cs_w1, g_csw1t, 256, 256, blk); return; }
    if (blk < 384)  { rp_t(cs_w2, g_csw2t, 128, 256, blk - 256); return; }
    if (blk < 416)  { rp_t(c1_w2, g_c1w2t, 128, 64, blk - 384); return; }
    if (blk < 432) {
        int g = (blk - 416) * 256 + t;
        int j = g & 1, o = (g >> 1) & 63, c2 = g >> 7;
        float v = s2_w2[o * 64 + 2 * c2 + j] * (s2_g2[o] * bnc);
        g_s2w2d[g] = f2pk(v, v);
        return;
    }
    if (blk < 464) {
        int g = (blk - 432) * 256 + t;
        int o = g >> 6, c = g & 63;
        g_s2w3p[((c >> 2) * 128 + o) * 4 + (c & 3)] = s2_w3[o * 64 + c];
        return;
    }
    if (blk < 720) {
        int i = blk - 464;
        s_buf[t] = k_w[t * 256 + i];
        __syncthreads();
        float acc = 0.f;
        for (int o = 0; o < 256; o++) acc += s_buf[o] * __ldg(q_w + o * 256 + t);
        g_Ap[((t >> 2) * 256 + i) * 4 + (t & 3)] = acc;
        float part = s_buf[t] * q_b[t];
#pragma unroll
        for (int off = 16; off; off >>= 1) part += __shfl_down_sync(0xffffffffu, part, off);
        if ((t & 31) == 0) s_red[t >> 5] = part;
        __syncthreads();
        if (t == 0) { float s = 0.f; for (int w = 0; w < 8; w++) s += s_red[w]; g_cvec[i] = s; }
        return;
    }
    if (blk < 728) {
        int b = blk - 720;
        for (int i = t; i < 512; i += 256) s_buf[i] = gf[b * 512 + i];
        __syncthreads();
        float a = cf_b1[t];
        const float* wr = cf_w1 + t * 512;
        for (int c = 0; c < 512; c++) a += wr[c] * s_buf[c];
        s_h[t] = fmaxf(a, 0.f);
        __syncthreads();
        if (t < 128) {
            float a2 = cf_b2[t];
            const float* w2r = cf_w2 + t * 256;
            for (int c = 0; c < 256; c++) a2 += w2r[c] * s_h[c];
            g_gvec[b * 128 + t] = a2;
        }
        return;
    }
    if (blk == 728) {
        float acc = 0.f;
        for (int o = 0; o < 256; o++) acc += __ldg(q_w + o * 256 + t) * k_b[o];
        g_vb[t] = acc;
        if (t == 0) {
            float s = 0.f;
            for (int o = 0; o < 256; o++) s += q_b[o] * k_b[o];
            g_s0[0] = s;
        }
        return;
    }
    for (int i = t; i < 576; i += 256) {
        int o = i / 9;
        g_w1f[i] = s2_w1[i] * (s2_g1[o] * bnc);
    }
    if (t < 64) {
        g_b1f[t] = s2_b1[t] * (s2_g1[t] * bnc) + s2_bb1[t];
        g_b2f[t] = s2_b2[t] * (s2_g2[t] * bnc) + s2_bb2[t];
    }
}

__global__ void k_prep2(const float* __restrict__ csb1) {
    __shared__ float gv[128];
    int b = blockIdx.x, t = threadIdx.x;
    if (t < 128) gv[t] = g_gvec[b * 128 + t];
    __syncthreads();
    float acc = csb1[t];
    for (int c = 0; c < 128; c++) acc += g_csw1t[(128 + c) * 256 + t] * gv[c];
    g_hg[b * 256 + t] = acc;
}

// ---------------- fused c1 + cs MLP (unchanged) ---------------------------
__global__ void __launch_bounds__(256) k_feat(const float* __restrict__ x,
                                              const float* __restrict__ c1w1,
                                              const float* __restrict__ c1b1,
                                              const float* __restrict__ c1b2,
                                              const float* __restrict__ csb2) {
    extern __shared__ __align__(16) float fm[];
    float* s_int = fm;
    float* s_ht  = fm + 128 * FS;
    float* s_h64 = s_ht;
    float* s_xyz = fm + 384 * FS;
    int t = threadIdx.x;
    int base = blockIdx.x * 32;
    int b = base >> 13;
    if (t < 96) s_xyz[t] = x[(size_t)base * 3 + t];
    __syncthreads();
    for (int i = 0; i < 8; i++) {
        int task = t + 256 * i;
        int p = task & 31, o = task >> 5;
        float a = c1b1[o];
        a += c1w1[o * 3 + 0] * s_xyz[p * 3 + 0];
        a += c1w1[o * 3 + 1] * s_xyz[p * 3 + 1];
        a += c1w1[o * 3 + 2] * s_xyz[p * 3 + 2];
        s_h64[o * FS + p] = fmaxf(a, 0.f);
    }
    __syncthreads();
    {
        int o0 = (t & 31) * 4, pg = t >> 5;
        ull acc[8];
#pragma unroll
        for (int i = 0; i < 8; i++) acc[i] = 0ull;
#pragma unroll 4
        for (int c = 0; c < 64; c++) {
            float4 w = *(const float4*)(g_c1w2t + c * 128 + o0);
            ull w0 = f2pk(w.x, w.x), w1 = f2pk(w.y, w.y);
            ull w2 = f2pk(w.z, w.z), w3 = f2pk(w.w, w.w);
            ulonglong2 v = *(const ulonglong2*)(s_h64 + c * FS + pg * 4);
            acc[0] = fma2(w0, v.x, acc[0]); acc[1] = fma2(w0, v.y, acc[1]);
            acc[2] = fma2(w1, v.x, acc[2]); acc[3] = fma2(w1, v.y, acc[3]);
            acc[4] = fma2(w2, v.x, acc[4]); acc[5] = fma2(w2, v.y, acc[5]);
            acc[6] = fma2(w3, v.x, acc[6]); acc[7] = fma2(w3, v.y, acc[7]);
        }
        float4 bq = *(const float4*)(c1b2 + o0);
        float bb[4] = { bq.x, bq.y, bq.z, bq.w };
        __syncthreads();
#pragma unroll
        for (int oi = 0; oi < 4; oi++) {
            ull bp = f2pk(bb[oi], bb[oi]);
            *(ull*)(s_int + (o0 + oi) * FS + pg * 4)     = addx2(acc[oi * 2], bp);
            *(ull*)(s_int + (o0 + oi) * FS + pg * 4 + 2) = addx2(acc[oi * 2 + 1], bp);
        }
    }
    __syncthreads();
    {
        int o0 = (t & 63) * 4, pg = t >> 6;
        ull acc[16];
#pragma unroll
        for (int i = 0; i < 16; i++) acc[i] = 0ull;
#pragma unroll 2
        for (int c = 0; c < 128; c++) {
            float4 w = *(const float4*)(g_csw1t + c * 256 + o0);
            ull w0 = f2pk(w.x, w.x), w1 = f2pk(w.y, w.y);
            ull w2 = f2pk(w.z, w.z), w3 = f2pk(w.w, w.w);
            ulonglong2 v01 = *(const ulonglong2*)(s_int + c * FS + pg * 8);
            ulonglong2 v23 = *(const ulonglong2*)(s_int + c * FS + pg * 8 + 4);
            acc[0]  = fma2(w0, v01.x, acc[0]);  acc[1]  = fma2(w0, v01.y, acc[1]);
            acc[2]  = fma2(w0, v23.x, acc[2]);  acc[3]  = fma2(w0, v23.y, acc[3]);
            acc[4]  = fma2(w1, v01.x, acc[4]);  acc[5]  = fma2(w1, v01.y, acc[5]);
            acc[6]  = fma2(w1, v23.x, acc[6]);  acc[7]  = fma2(w1, v23.y, acc[7]);
            acc[8]  = fma2(w2, v01.x, acc[8]);  acc[9]  = fma2(w2, v01.y, acc[9]);
            acc[10] = fma2(w2, v23.x, acc[10]); acc[11] = fma2(w2, v23.y, acc[11]);
            acc[12] = fma2(w3, v01.x, acc[12]); acc[13] = fma2(w3, v01.y, acc[13]);
            acc[14] = fma2(w3, v23.x, acc[14]); acc[15] = fma2(w3, v23.y, acc[15]);
        }
        float4 bq = *(const float4*)(g_hg + b * 256 + o0);
        float bb[4] = { bq.x, bq.y, bq.z, bq.w };
        __syncthreads();
#pragma unroll
        for (int oi = 0; oi < 4; oi++) {
#pragma unroll
            for (int g = 0; g < 4; g++) {
                float lo, hi; f2up(acc[oi * 4 + g], lo, hi);
                lo = fmaxf(lo + bb[oi], 0.f); hi = fmaxf(hi + bb[oi], 0.f);
                *(ull*)(s_ht + (o0 + oi) * FS + pg * 8 + g * 2) = f2pk(lo, hi);
            }
        }
    }
    __syncthreads();
    {
        int o0 = (t & 31) * 4, pg = t >> 5;
        ull acc[8];
#pragma unroll
        for (int i = 0; i < 8; i++) acc[i] = 0ull;
#pragma unroll 2
        for (int c = 0; c < 256; c++) {
            float4 w = *(const float4*)(g_csw2t + c * 128 + o0);
            ull w0 = f2pk(w.x, w.x), w1 = f2pk(w.y, w.y);
            ull w2 = f2pk(w.z, w.z), w3 = f2pk(w.w, w.w);
            ulonglong2 v = *(const ulonglong2*)(s_ht + c * FS + pg * 4);
            acc[0] = fma2(w0, v.x, acc[0]); acc[1] = fma2(w0, v.y, acc[1]);
            acc[2] = fma2(w1, v.x, acc[2]); acc[3] = fma2(w1, v.y, acc[3]);
            acc[4] = fma2(w2, v.x, acc[4]); acc[5] = fma2(w2, v.y, acc[5]);
            acc[6] = fma2(w3, v.x, acc[6]); acc[7] = fma2(w3, v.y, acc[7]);
        }
        float4 bq = *(const float4*)(csb2 + o0);
        float bb[4] = { bq.x, bq.y, bq.z, bq.w };
#pragma unroll
        for (int pp = 0; pp < 4; pp++) {
            float4 val;
            float lo, hi;
            f2up(acc[0 + (pp >> 1)], lo, hi); val.x = ((pp & 1) ? hi : lo) + bb[0];
            f2up(acc[2 + (pp >> 1)], lo, hi); val.y = ((pp & 1) ? hi : lo) + bb[1];
            f2up(acc[4 + (pp >> 1)], lo, hi); val.z = ((pp & 1) ? hi : lo) + bb[2];
            f2up(acc[6 + (pp >> 1)], lo, hi); val.w = ((pp & 1) ? hi : lo) + bb[3];
            *(float4*)(g_f2 + (size_t)(base + pg * 4 + pp) * 128 + o0) = val;
        }
    }
}

// ---------------- FPS v4: 512 thr x 16 pts; ONE barrier; REDUX pairs ------
__global__ void __launch_bounds__(512, 1) k_fps(const float* __restrict__ x,
                                                float* __restrict__ out_down) {
    extern __shared__ float sp[];
    float* sxx = sp;
    float* syy = sp + NP;
    float* szz = sp + 2 * NP;
    __shared__ unsigned s_bv[2][16];
    __shared__ unsigned s_bi[2][16];
    int b = blockIdx.x, t = threadIdx.x, lane = t & 31, wid = t >> 5;
    const float* xb = x + (size_t)b * NP * 3;
    for (int i = t; i < NP; i += 512) {
        sxx[i] = xb[3 * i]; syy[i] = xb[3 * i + 1]; szz[i] = xb[3 * i + 2];
    }
    __syncthreads();
    float cx = sxx[0], cy = syy[0], cz = szz[0];
    if (t == 0) {
        int o3 = b * MP * 3;
        g_down[o3 + 0] = cx; g_down[o3 + 1] = cy; g_down[o3 + 2] = cz;
        out_down[o3 + 0] = cx; out_down[o3 + 1] = cy; out_down[o3 + 2] = cz;
    }
    int base = t * 16;
    ull pxp[8], pyp[8], pzp[8];
    float md[16];
#pragma unroll
    for (int j = 0; j < 8; j++) {
        pxp[j] = *(const ull*)(sxx + base + 2 * j);
        pyp[j] = *(const ull*)(syy + base + 2 * j);
        pzp[j] = *(const ull*)(szz + base + 2 * j);
        md[2 * j] = 1e10f; md[2 * j + 1] = 1e10f;
    }
    int buf = 0;
    for (int it = 1; it < MP; it++) {
        ull ncx = f2pk(-cx, -cx), ncy = f2pk(-cy, -cy), ncz = f2pk(-cz, -cz);
#pragma unroll
        for (int j = 0; j < 8; j++) {
            ull dx = addx2(pxp[j], ncx);
            ull dy = addx2(pyp[j], ncy);
            ull dz = addx2(pzp[j], ncz);
            ull s = addx2(addx2(mulx2(dx, dx), mulx2(dy, dy)), mulx2(dz, dz));
            float lo, hi; f2up(s, lo, hi);
            md[2 * j]     = fminf(md[2 * j], lo);
            md[2 * j + 1] = fminf(md[2 * j + 1], hi);
        }
        float a0 = fmaxf(md[0], md[1]),  a1 = fmaxf(md[2], md[3]);
        float a2 = fmaxf(md[4], md[5]),  a3 = fmaxf(md[6], md[7]);
        float a4 = fmaxf(md[8], md[9]),  a5 = fmaxf(md[10], md[11]);
        float a6 = fmaxf(md[12], md[13]), a7 = fmaxf(md[14], md[15]);
        float b0 = fmaxf(a0, a1), b1 = fmaxf(a2, a3);
        float b2 = fmaxf(a4, a5), b3 = fmaxf(a6, a7);
        float m = fmaxf(fmaxf(b0, b1), fmaxf(b2, b3));
        unsigned wm = __reduce_max_sync(0xffffffffu, __float_as_uint(m));
        unsigned li = 0xFFFFFFFFu;
#pragma unroll
        for (int j = 15; j >= 0; j--)
            li = (__float_as_uint(md[j]) == wm) ? (unsigned)(base + j) : li;
        unsigned wi = __reduce_min_sync(0xffffffffu, li);
        if (lane == 0) { s_bv[buf][wid] = wm; s_bi[buf][wid] = wi; }
        __syncthreads();
        unsigned v = s_bv[buf][lane & 15];
        unsigned i2 = s_bi[buf][lane & 15];
        unsigned gm = __reduce_max_sync(0xffffffffu, v);
        unsigned cand = (v == gm) ? i2 : 0xFFFFFFFFu;
        unsigned gi = __reduce_min_sync(0xffffffffu, cand);
        cx = sxx[gi]; cy = syy[gi]; cz = szz[gi];
        if (t == 0) {
            int o3 = (b * MP + it) * 3;
            g_down[o3 + 0] = cx; g_down[o3 + 1] = cy; g_down[o3 + 2] = cz;
            out_down[o3 + 0] = cx; out_down[o3 + 1] = cy; out_down[o3 + 2] = cz;
        }
        buf ^= 1;
    }
}

// ---------------- KNN v2 (unchanged) ---------------------------------------
__global__ void __launch_bounds__(128) k_knn(const float* __restrict__ x) {
    extern __shared__ float kp[];
    float* sxx = kp;
    float* syy = kp + NP;
    float* szz = kp + 2 * NP;
    float* sdl = kp + 3 * NP;
    int*   sil = (int*)(kp + 3 * NP + 2176);
    int t = threadIdx.x;
    int q = t & 63, half = t >> 6;
    int gid = blockIdx.x * 64 + q;
    int b = gid >> 10;
    const float* xb = x + (size_t)b * NP * 3;
    for (int i = t; i < NP; i += 128) {
        sxx[i] = xb[3 * i]; syy[i] = xb[3 * i + 1]; szz[i] = xb[3 * i + 2];
    }
    __syncthreads();
    float qx = g_down[gid * 3 + 0], qy = g_down[gid * 3 + 1], qz = g_down[gid * 3 + 2];
    float sd = __fadd_rn(__fadd_rn(__fmul_rn(qx, qx), __fmul_rn(qy, qy)), __fmul_rn(qz, qz));
    ull qxp = f2pk(qx, qx), qyp = f2pk(qy, qy), qzp = f2pk(qz, qz);
    ull sdp = f2pk(sd, sd), n2p = f2pk(-2.f, -2.f);
    float dist[17]; int ind[17];
#pragma unroll
    for (int i = 0; i < 17; i++) { dist[i] = 3.4e38f; ind[i] = 0; }
    int n0 = half * 4096;
    for (int n = n0; n < n0 + 4096; n += 2) {
        ull axp = *(const ull*)(sxx + n);
        ull ayp = *(const ull*)(syy + n);
        ull azp = *(const ull*)(szz + n);
        ull sn = addx2(addx2(mulx2(axp, axp), mulx2(ayp, ayp)), mulx2(azp, azp));
        ull dt = addx2(addx2(mulx2(qxp, axp), mulx2(qyp, ayp)), mulx2(qzp, azp));
        ull d2p = addx2(addx2(sdp, sn), mulx2(n2p, dt));
        float dlo, dhi; f2up(d2p, dlo, dhi);
#pragma unroll
        for (int h = 0; h < 2; h++) {
            float d2 = h ? dhi : dlo;
            int ni = n + h;
            if (d2 < dist[16]) {
                int pos = 0;
#pragma unroll
                for (int s = 0; s < 17; s++) pos += (dist[s] <= d2) ? 1 : 0;
#pragma unroll
                for (int s = 16; s > 0; s--) {
                    if (s > pos) { dist[s] = dist[s - 1]; ind[s] = ind[s - 1]; }
                    else if (s == pos) { dist[s] = d2; ind[s] = ni; }
                }
                if (pos == 0) { dist[0] = d2; ind[0] = ni; }
            }
        }
    }
    {
        float* dptr = sdl + (half * 64 + q) * 17;
        int*   iptr = sil + (half * 64 + q) * 17;
#pragma unroll
        for (int s = 0; s < 17; s++) { dptr[s] = dist[s]; iptr[s] = ind[s]; }
    }
    __syncthreads();
    if (t < 64) {
        const float* dA = sdl + q * 17;
        const float* dB = sdl + (64 + q) * 17;
        const int*   iA = sil + q * 17;
        const int*   iB = sil + (64 + q) * 17;
        int ia = 0, ib = 0;
        int* outp = g_knn + (size_t)gid * 17;
#pragma unroll
        for (int k = 0; k < 17; k++) {
            float da = dA[ia], db = dB[ib];
            bool takeA = (da <= db);
            outp[k] = takeA ? iA[ia] : iB[ib];
            ia += takeA ? 1 : 0;
            ib += takeA ? 0 : 1;
        }
    }
}

// ---------------- attention v3: G=4 m's, 512 threads ----------------------
// smem floats: feat[68][128]@0  h1i[2][17][128]@8704  h2i[2][17][128]@13056
//   fr2[4][128]@17408  us[4][256]@17920  zs[4][64][2]@18944
//   knnx@19456(204) dwn@19660(12) lgA@19672(64) lgB@19736(4) lgC@19740(4) sidx@19744(68)
__global__ void __launch_bounds__(512) k_attn(
    const float* __restrict__ x,
    const float* __restrict__ w3, const float* __restrict__ b3,
    float* __restrict__ out_new)
{
    extern __shared__ __align__(16) float sm[];
    float* feat = sm;
    float* h1i  = sm + 8704;
    float* h2i  = sm + 13056;
    float* fr2  = sm + 17408;
    float* us   = sm + 17920;
    float* zs   = sm + 18944;
    float* knnx = sm + 19456;
    float* dwn  = sm + 19660;
    float* lgA  = sm + 19672;
    float* lgB  = sm + 19736;
    float* lgC  = sm + 19740;
    int*   sidx = (int*)(sm + 19744);

    int t = threadIdx.x;
    int wid = t >> 5, lane = t & 31;
    int bm0 = blockIdx.x * 4;
    int b = bm0 >> 10;
    const float* xb = x + (size_t)b * NP * 3;

    if (t < 68) {
        int id = g_knn[(size_t)bm0 * 17 + t];
        sidx[t] = id;
        knnx[t * 3 + 0] = xb[id * 3 + 0];
        knnx[t * 3 + 1] = xb[id * 3 + 1];
        knnx[t * 3 + 2] = xb[id * 3 + 2];
    }
    if (t < 12) dwn[t] = g_down[(size_t)bm0 * 3 + t];
    __syncthreads();

    // gather knn_f -> feat
    for (int r = wid; r < 68; r += 16) {
        const float4* src = (const float4*)(g_f2 + ((size_t)(b * NP) + sidx[r]) * 128);
        ((float4*)(feat + r * 128))[lane] = src[lane];
    }

    // h1: 68 rows x 64 = 4352 tasks; pair-interleaved store
    for (int i = 0; i < 9; i++) {
        int task = t + 512 * i;
        if (task < 4352) {
            int o = task & 63, row = task >> 6;     // row 0..67
            int mi = row / 17;
            int pr = row - 17 * mi;
            int pg = mi >> 1, j = mi & 1;
            const float* kpp = knnx + row * 3;
            const float* dp = dwn + mi * 3;
            float r0 = dp[0], r1 = dp[1], r2v = dp[2];
            float r3 = kpp[0], r4 = kpp[1], r5 = kpp[2];
            const float* w = g_w1f + o * 9;
            float a = g_b1f[o];
            a += w[0] * r0 + w[1] * r1 + w[2] * r2v;
            a += w[3] * r3 + w[4] * r4 + w[5] * r5;
            a += w[6] * (r0 - r3) + w[7] * (r1 - r4) + w[8] * (r2v - r5);
            a = a > 0.f ? a : 0.01f * a;
            h1i[(pg * 17 + pr) * 128 + o * 2 + j] = a;
        }
    }
    __syncthreads();
    // h2: 2 pg x 17 prow x 32 = 1088 tasks
    {
        const ulonglong2* w2d = (const ulonglong2*)g_s2w2d;
        for (int i = 0; i < 3; i++) {
            int task = t + 512 * i;
            if (task < 1088) {
                int o = task & 31;
                int pr2 = task >> 5;                 // 0..33
                int pg = (pr2 >= 17) ? 1 : 0;
                int prow = pr2 - 17 * pg;
                int o2 = o + 32;
                const ulonglong2* hv = (const ulonglong2*)(h1i + (pg * 17 + prow) * 128);
                float ba = g_b2f[o], bb2v = g_b2f[o2];
                ull accA = f2pk(ba, ba), accB = f2pk(bb2v, bb2v);
#pragma unroll 4
                for (int c2 = 0; c2 < 32; c2++) {
                    ulonglong2 v = hv[c2];
                    ulonglong2 wA = w2d[c2 * 64 + o];
                    ulonglong2 wB = w2d[c2 * 64 + o2];
                    accA = fma2(wA.x, v.x, accA); accA = fma2(wA.y, v.y, accA);
                    accB = fma2(wB.x, v.x, accB); accB = fma2(wB.y, v.y, accB);
                }
                float* hrow = h2i + (pg * 17 + prow) * 128;
                float a0, a1; f2up(accA, a0, a1);
                a0 = a0 > 0.f ? a0 : 0.01f * a0;
                a1 = a1 > 0.f ? a1 : 0.01f * a1;
                hrow[o * 2]     = a0;
                hrow[o * 2 + 1] = a1;
                f2up(accB, a0, a1);
                a0 = a0 > 0.f ? a0 : 0.01f * a0;
                a1 = a1 > 0.f ? a1 : 0.01f * a1;
                hrow[o2 * 2]     = a0;
                hrow[o2 * 2 + 1] = a1;
            }
        }
    }
    __syncthreads();
    // r2 for the 4 query rows: 512 tasks
    {
        int mi = t >> 7, o = t & 127;
        int pg = mi >> 1, j = mi & 1;
        const ulonglong2* hc2 = (const ulonglong2*)(h2i + pg * 17 * 128);  // prow 0
        float acc = b3[o];
#pragma unroll 4
        for (int c4 = 0; c4 < 16; c4++) {
            float4 w = ((const float4*)g_s2w3p)[c4 * 128 + o];
            ulonglong2 p0 = hc2[2 * c4], p1 = hc2[2 * c4 + 1];
            float l0, h0v, l1, h1v, l2, h2v, l3, h3v;
            f2up(p0.x, l0, h0v); f2up(p0.y, l1, h1v);
            f2up(p1.x, l2, h2v); f2up(p1.y, l3, h3v);
            float v0 = j ? h0v : l0, v1 = j ? h1v : l1;
            float v2 = j ? h2v : l2, v3 = j ? h3v : l3;
            acc += w.x * v0 + w.y * v1 + w.z * v2 + w.w * v3;
        }
        fr2[mi * 128 + o] = acc;
    }
    __syncthreads();
    // u_m = A f_m0 + c  (each half of the block handles 2 m's)
    {
        int ch = t & 255, grp = t >> 8;             // grp 0..1
        int m0 = grp * 2, m1 = grp * 2 + 1;
        const float4* ap = (const float4*)g_Ap;
        float a0 = 0.f, a1 = 0.f;
        for (int c4 = 0; c4 < 32; c4++) {
            float4 w = ap[c4 * 256 + ch];
            float4 v0 = *(const float4*)(feat + m0 * 17 * 128 + c4 * 4);
            float4 v1 = *(const float4*)(feat + m1 * 17 * 128 + c4 * 4);
            a0 += w.x * v0.x + w.y * v0.y + w.z * v0.z + w.w * v0.w;
            a1 += w.x * v1.x + w.y * v1.y + w.z * v1.z + w.w * v1.w;
        }
        for (int c4 = 0; c4 < 32; c4++) {
            float4 w = ap[(32 + c4) * 256 + ch];
            float4 v0 = *(const float4*)(fr2 + m0 * 128 + c4 * 4);
            float4 v1 = *(const float4*)(fr2 + m1 * 128 + c4 * 4);
            a0 += w.x * v0.x + w.y * v0.y + w.z * v0.z + w.w * v0.w;
            a1 += w.x * v1.x + w.y * v1.y + w.z * v1.z + w.w * v1.w;
        }
        float cv = g_cvec[ch];
        us[m0 * 256 + ch] = a0 + cv;
        us[m1 * 256 + ch] = a1 + cv;
    }
    __syncthreads();
    // z_m = W3^T u_hi : 512 tasks
    {
        int mi = t >> 7, rem = t & 127, c = rem >> 1, oh = rem & 1;
        const float* ur = us + mi * 256 + 128 + oh * 64;
        float acc = 0.f;
#pragma unroll 4
        for (int o = 0; o < 64; o++) acc += __ldg(w3 + (oh * 64 + o) * 64 + c) * ur[o];
        zs[(mi * 64 + c) * 2 + oh] = acc;
    }
    __syncthreads();
    // logits: 64 typeA + 4 typeB + 4 typeC
    for (int task = wid; task < 72; task += 16) {
        float s = 0.f;
        if (task < 64) {
            int mi = task >> 4, j = task & 15;
            const float* uf = us + mi * 256;
            const float* fr = feat + (mi * 17 + 1 + j) * 128;
#pragma unroll
            for (int k = 0; k < 4; k++) { int o = lane + 32 * k; s += uf[o] * fr[o]; }
            const float* hj = h2i + ((mi >> 1) * 17 + 1 + j) * 128;
#pragma unroll
            for (int k = 0; k < 2; k++) {
                int c = lane + 32 * k;
                s += (zs[(mi * 64 + c) * 2] + zs[(mi * 64 + c) * 2 + 1]) * hj[c * 2 + (mi & 1)];
            }
        } else if (task < 68) {
            int mi = task - 64;
            const float* fl = feat + mi * 17 * 128;
            const float* fh = fr2 + mi * 128;
#pragma unroll
            for (int k = 0; k < 4; k++) {
                int o = lane + 32 * k;
                s += __ldg(&g_vb[o]) * fl[o] + __ldg(&g_vb[128 + o]) * fh[o];
            }
        } else {
            int mi = task - 68;
            const float* uh = us + mi * 256 + 128;
#pragma unroll
            for (int k = 0; k < 4; k++) { int o = lane + 32 * k; s += uh[o] * __ldg(b3 + o); }
        }
#pragma unroll
        for (int off = 16; off; off >>= 1) s += __shfl_down_sync(0xffffffffu, s, off);
        if (lane == 0) {
            if (task < 64) lgA[task] = s;
            else if (task < 68) lgB[task - 64] = s;
            else lgC[task - 68] = s;
        }
    }
    __syncthreads();

    if (t < 4) {
        float ex = lgB[t] + lgC[t] + g_s0[0];
        float l[16], mx = -3.4e38f;
#pragma unroll
        for (int j = 0; j < 16; j++) { l[j] = lgA[t * 16 + j] + ex; mx = fmaxf(mx, l[j]); }
        float sum = 0.f;
#pragma unroll
        for (int j = 0; j < 16; j++) { l[j] = expf(l[j] - mx); sum += l[j]; }
        float inv = 1.f / sum;
        float nx = 0.f, ny = 0.f, nz = 0.f;
#pragma unroll
        for (int j = 0; j < 16; j++) {
            float w = l[j] * inv;
            const float* kpp = knnx + (t * 17 + 1 + j) * 3;
            nx += w * kpp[0]; ny += w * kpp[1]; nz += w * kpp[2];
        }
        float* po = out_new + (size_t)(bm0 + t) * 3;
        po[0] = nx; po[1] = ny; po[2] = nz;
    }
}

// ---------------- launch ---------------------------------------------------
extern "C" void kernel_launch(void* const* d_in, const int* in_sizes, int n_in,
                              void* d_out, int out_size) {
    const float* x      = (const float*)d_in[0];
    const float* gf     = (const float*)d_in[1];
    const float* c1_w1  = (const float*)d_in[2];
    const float* c1_b1  = (const float*)d_in[3];
    const float* c1_w2  = (const float*)d_in[4];
    const float* c1_b2  = (const float*)d_in[5];
    const float* cf_w1  = (const float*)d_in[6];
    const float* cf_b1  = (const float*)d_in[7];
    const float* cf_w2  = (const float*)d_in[8];
    const float* cf_b2  = (const float*)d_in[9];
    const float* cs_w1  = (const float*)d_in[10];
    const float* cs_b1  = (const float*)d_in[11];
    const float* cs_w2  = (const float*)d_in[12];
    const float* cs_b2  = (const float*)d_in[13];
    const float* s2_w1  = (const float*)d_in[14];
    const float* s2_b1  = (const float*)d_in[15];
    const float* s2_g1  = (const float*)d_in[16];
    const float* s2_bb1 = (const float*)d_in[17];
    const float* s2_w2  = (const float*)d_in[18];
    const float* s2_b2  = (const float*)d_in[19];
    const float* s2_g2  = (const float*)d_in[20];
    const float* s2_bb2 = (const float*)d_in[21];
    const float* s2_w3  = (const float*)d_in[22];
    const float* s2_b3  = (const float*)d_in[23];
    const float* q_w    = (const float*)d_in[24];
    const float* q_b    = (const float*)d_in[25];
    const float* k_w    = (const float*)d_in[26];
    const float* k_b    = (const float*)d_in[27];
    float* out = (float*)d_out;

    static bool s_init = false;
    static cudaStream_t st;
    static cudaEvent_t evF, evD;
    const int FEAT_SMEM = (384 * FS + 96) * 4;
    const int ATTN_SMEM = 19812 * 4;
    const int KNN_SMEM  = (3 * NP + 2 * 2176) * 4;
    if (!s_init) {
        cudaStreamCreateWithFlags(&st, cudaStreamNonBlocking);
        cudaEventCreateWithFlags(&evF, cudaEventDisableTiming);
        cudaEventCreateWithFlags(&evD, cudaEventDisableTiming);
        cudaFuncSetAttribute(k_feat, cudaFuncAttributeMaxDynamicSharedMemorySize, FEAT_SMEM);
        cudaFuncSetAttribute(k_knn,  cudaFuncAttributeMaxDynamicSharedMemorySize, KNN_SMEM);
        cudaFuncSetAttribute(k_fps,  cudaFuncAttributeMaxDynamicSharedMemorySize, NP * 3 * 4);
        cudaFuncSetAttribute(k_attn, cudaFuncAttributeMaxDynamicSharedMemorySize, ATTN_SMEM);
        s_init = true;
    }

    cudaEventRecord(evF, 0);
    cudaStreamWaitEvent(st, evF, 0);

    k_prep<<<730, 256>>>(cs_w1, cs_w2, c1_w2,                         // #1
                         s2_w1, s2_b1, s2_g1, s2_bb1,
                         s2_w2, s2_b2, s2_g2, s2_bb2, s2_w3,
                         q_w, k_w, q_b, k_b,
                         gf, cf_w1, cf_b1, cf_w2, cf_b2);
    k_prep2<<<BN, 256>>>(cs_b1);                                      // #2
    k_feat<<<(BN * NP) / 32, 256, FEAT_SMEM>>>(x,                     // #3
        c1_w1, c1_b1, c1_b2, cs_b2);

    k_fps<<<BN, 512, NP * 3 * 4, st>>>(x, out);                       // #4 <- profiled
    k_knn<<<(BN * MP) / 64, 128, KNN_SMEM, st>>>(x);                  // #5
    cudaEventRecord(evD, st);
    cudaStreamWaitEvent(0, evD, 0);
    k_attn<<<(BN * MP) / 4, 512, ATTN_SMEM>>>(x, s2_w3, s2_b3,        // #6
        out + (size_t)BN * MP * 3);
}

// round 11
// speedup vs baseline: 1.0244x; 1.0244x over previous
#include <cuda_runtime.h>
#include <math.h>

#define BN 8
#define NP 8192
#define MP 1024
#define KNB 17
#define FS 36

typedef unsigned long long ull;

// ---------------- scratch ----------------
__device__ float g_gvec[BN * 128];
__device__ float g_f2[BN * NP * 128];
__device__ float g_down[BN * MP * 3];
__device__ int   g_knn[BN * MP * KNB];
__device__ float g_csw1t[256 * 256];
__device__ float g_csw2t[256 * 128];
__device__ float g_c1w2t[64 * 128];
__device__ float g_hg[BN * 256];
__device__ ull   g_s2w2d[64 * 64];
__device__ float g_s2w3p[128 * 64];
__device__ float g_w1f[64 * 9];
__device__ float g_b1f[64];
__device__ float g_b2f[64];
__device__ float g_Ap[256 * 256];
__device__ float g_cvec[256];
__device__ float g_vb[256];
__device__ float g_s0[1];

__device__ __forceinline__ ull f2pk(float lo, float hi) {
    ull r; asm("mov.b64 %0,{%1,%2};" : "=l"(r) : "f"(lo), "f"(hi)); return r;
}
__device__ __forceinline__ void f2up(ull v, float& lo, float& hi) {
    asm("mov.b64 {%0,%1},%2;" : "=f"(lo), "=f"(hi) : "l"(v));
}
__device__ __forceinline__ ull addx2(ull a, ull b) {
    ull r; asm("add.rn.f32x2 %0,%1,%2;" : "=l"(r) : "l"(a), "l"(b)); return r;
}
__device__ __forceinline__ ull mulx2(ull a, ull b) {
    ull r; asm("mul.rn.f32x2 %0,%1,%2;" : "=l"(r) : "l"(a), "l"(b)); return r;
}
__device__ __forceinline__ ull fma2(ull a, ull b, ull c) {
    ull r; asm("fma.rn.f32x2 %0,%1,%2,%3;" : "=l"(r) : "l"(a), "l"(b), "l"(c)); return r;
}

// ---------------- prep ----------------------------------------------------
__device__ __forceinline__ void rp_t(const float* __restrict__ w, float* __restrict__ o,
                                     int O, int C, int blk) {
    int g = blk * 256 + threadIdx.x;
    if (g >= O * C) return;
    int c = g / O, oo = g - c * O;
    o[c * O + oo] = w[oo * C + c];
}

__global__ void k_prep(const float* __restrict__ cs_w1, const float* __restrict__ cs_w2,
                       const float* __restrict__ c1_w2,
                       const float* __restrict__ s2_w1, const float* __restrict__ s2_b1,
                       const float* __restrict__ s2_g1, const float* __restrict__ s2_bb1,
                       const float* __restrict__ s2_w2, const float* __restrict__ s2_b2,
                       const float* __restrict__ s2_g2, const float* __restrict__ s2_bb2,
                       const float* __restrict__ s2_w3,
                       const float* __restrict__ q_w, const float* __restrict__ k_w,
                       const float* __restrict__ q_b, const float* __restrict__ k_b,
                       const float* __restrict__ gf,
                       const float* __restrict__ cf_w1, const float* __restrict__ cf_b1,
                       const float* __restrict__ cf_w2, const float* __restrict__ cf_b2) {
    __shared__ float s_buf[512];
    __shared__ float s_h[256];
    __shared__ float s_red[8];
    const float bnc = 1.f / sqrtf(1.0f + 1e-5f);
    int blk = blockIdx.x, t = threadIdx.x;
    if (blk < 256)  { rp_t(cs_w1, g_csw1t, 256, 256, blk); return; }
    if (blk < 384)  { rp_t(cs_w2, g_csw2t, 128, 256, blk - 256); return; }
    if (blk < 416)  { rp_t(c1_w2, g_c1w2t, 128, 64, blk - 384); return; }
    if (blk < 432) {
        int g = (blk - 416) * 256 + t;
        int j = g & 1, o = (g >> 1) & 63, c2 = g >> 7;
        float v = s2_w2[o * 64 + 2 * c2 + j] * (s2_g2[o] * bnc);
        g_s2w2d[g] = f2pk(v, v);
        return;
    }
    if (blk < 464) {
        int g = (blk - 432) * 256 + t;
        int o = g >> 6, c = g & 63;
        g_s2w3p[((c >> 2) * 128 + o) * 4 + (c & 3)] = s2_w3[o * 64 + c];
        return;
    }
    if (blk < 720) {
        int i = blk - 464;
        s_buf[t] = k_w[t * 256 + i];
        __syncthreads();
        float acc = 0.f;
        for (int o = 0; o < 256; o++) acc += s_buf[o] * __ldg(q_w + o * 256 + t);
        g_Ap[((t >> 2) * 256 + i) * 4 + (t & 3)] = acc;
        float part = s_buf[t] * q_b[t];
#pragma unroll
        for (int off = 16; off; off >>= 1) part += __shfl_down_sync(0xffffffffu, part, off);
        if ((t & 31) == 0) s_red[t >> 5] = part;
        __syncthreads();
        if (t == 0) { float s = 0.f; for (int w = 0; w < 8; w++) s += s_red[w]; g_cvec[i] = s; }
        return;
    }
    if (blk < 728) {
        int b = blk - 720;
        for (int i = t; i < 512; i += 256) s_buf[i] = gf[b * 512 + i];
        __syncthreads();
        float a = cf_b1[t];
        const float* wr = cf_w1 + t * 512;
        for (int c = 0; c < 512; c++) a += wr[c] * s_buf[c];
        s_h[t] = fmaxf(a, 0.f);
        __syncthreads();
        if (t < 128) {
            float a2 = cf_b2[t];
            const float* w2r = cf_w2 + t * 256;
            for (int c = 0; c < 256; c++) a2 += w2r[c] * s_h[c];
            g_gvec[b * 128 + t] = a2;
        }
        return;
    }
    if (blk == 728) {
        float acc = 0.f;
        for (int o = 0; o < 256; o++) acc += __ldg(q_w + o * 256 + t) * k_b[o];
        g_vb[t] = acc;
        if (t == 0) {
            float s = 0.f;
            for (int o = 0; o < 256; o++) s += q_b[o] * k_b[o];
            g_s0[0] = s;
        }
        return;
    }
    for (int i = t; i < 576; i += 256) {
        int o = i / 9;
        g_w1f[i] = s2_w1[i] * (s2_g1[o] * bnc);
    }
    if (t < 64) {
        g_b1f[t] = s2_b1[t] * (s2_g1[t] * bnc) + s2_bb1[t];
        g_b2f[t] = s2_b2[t] * (s2_g2[t] * bnc) + s2_bb2[t];
    }
}

__global__ void k_prep2(const float* __restrict__ csb1) {
    __shared__ float gv[128];
    int b = blockIdx.x, t = threadIdx.x;
    if (t < 128) gv[t] = g_gvec[b * 128 + t];
    __syncthreads();
    float acc = csb1[t];
    for (int c = 0; c < 128; c++) acc += g_csw1t[(128 + c) * 256 + t] * gv[c];
    g_hg[b * 256 + t] = acc;
}

// ---------------- fused c1 + cs MLP (unchanged) ---------------------------
__global__ void __launch_bounds__(256) k_feat(const float* __restrict__ x,
                                              const float* __restrict__ c1w1,
                                              const float* __restrict__ c1b1,
                                              const float* __restrict__ c1b2,
                                              const float* __restrict__ csb2) {
    extern __shared__ __align__(16) float fm[];
    float* s_int = fm;
    float* s_ht  = fm + 128 * FS;
    float* s_h64 = s_ht;
    float* s_xyz = fm + 384 * FS;
    int t = threadIdx.x;
    int base = blockIdx.x * 32;
    int b = base >> 13;
    if (t < 96) s_xyz[t] = x[(size_t)base * 3 + t];
    __syncthreads();
    for (int i = 0; i < 8; i++) {
        int task = t + 256 * i;
        int p = task & 31, o = task >> 5;
        float a = c1b1[o];
        a += c1w1[o * 3 + 0] * s_xyz[p * 3 + 0];
        a += c1w1[o * 3 + 1] * s_xyz[p * 3 + 1];
        a += c1w1[o * 3 + 2] * s_xyz[p * 3 + 2];
        s_h64[o * FS + p] = fmaxf(a, 0.f);
    }
    __syncthreads();
    {
        int o0 = (t & 31) * 4, pg = t >> 5;
        ull acc[8];
#pragma unroll
        for (int i = 0; i < 8; i++) acc[i] = 0ull;
#pragma unroll 4
        for (int c = 0; c < 64; c++) {
            float4 w = *(const float4*)(g_c1w2t + c * 128 + o0);
            ull w0 = f2pk(w.x, w.x), w1 = f2pk(w.y, w.y);
            ull w2 = f2pk(w.z, w.z), w3 = f2pk(w.w, w.w);
            ulonglong2 v = *(const ulonglong2*)(s_h64 + c * FS + pg * 4);
            acc[0] = fma2(w0, v.x, acc[0]); acc[1] = fma2(w0, v.y, acc[1]);
            acc[2] = fma2(w1, v.x, acc[2]); acc[3] = fma2(w1, v.y, acc[3]);
            acc[4] = fma2(w2, v.x, acc[4]); acc[5] = fma2(w2, v.y, acc[5]);
            acc[6] = fma2(w3, v.x, acc[6]); acc[7] = fma2(w3, v.y, acc[7]);
        }
        float4 bq = *(const float4*)(c1b2 + o0);
        float bb[4] = { bq.x, bq.y, bq.z, bq.w };
        __syncthreads();
#pragma unroll
        for (int oi = 0; oi < 4; oi++) {
            ull bp = f2pk(bb[oi], bb[oi]);
            *(ull*)(s_int + (o0 + oi) * FS + pg * 4)     = addx2(acc[oi * 2], bp);
            *(ull*)(s_int + (o0 + oi) * FS + pg * 4 + 2) = addx2(acc[oi * 2 + 1], bp);
        }
    }
    __syncthreads();
    {
        int o0 = (t & 63) * 4, pg = t >> 6;
        ull acc[16];
#pragma unroll
        for (int i = 0; i < 16; i++) acc[i] = 0ull;
#pragma unroll 2
        for (int c = 0; c < 128; c++) {
            float4 w = *(const float4*)(g_csw1t + c * 256 + o0);
            ull w0 = f2pk(w.x, w.x), w1 = f2pk(w.y, w.y);
            ull w2 = f2pk(w.z, w.z), w3 = f2pk(w.w, w.w);
            ulonglong2 v01 = *(const ulonglong2*)(s_int + c * FS + pg * 8);
            ulonglong2 v23 = *(const ulonglong2*)(s_int + c * FS + pg * 8 + 4);
            acc[0]  = fma2(w0, v01.x, acc[0]);  acc[1]  = fma2(w0, v01.y, acc[1]);
            acc[2]  = fma2(w0, v23.x, acc[2]);  acc[3]  = fma2(w0, v23.y, acc[3]);
            acc[4]  = fma2(w1, v01.x, acc[4]);  acc[5]  = fma2(w1, v01.y, acc[5]);
            acc[6]  = fma2(w1, v23.x, acc[6]);  acc[7]  = fma2(w1, v23.y, acc[7]);
            acc[8]  = fma2(w2, v01.x, acc[8]);  acc[9]  = fma2(w2, v01.y, acc[9]);
            acc[10] = fma2(w2, v23.x, acc[10]); acc[11] = fma2(w2, v23.y, acc[11]);
            acc[12] = fma2(w3, v01.x, acc[12]); acc[13] = fma2(w3, v01.y, acc[13]);
            acc[14] = fma2(w3, v23.x, acc[14]); acc[15] = fma2(w3, v23.y, acc[15]);
        }
        float4 bq = *(const float4*)(g_hg + b * 256 + o0);
        float bb[4] = { bq.x, bq.y, bq.z, bq.w };
        __syncthreads();
#pragma unroll
        for (int oi = 0; oi < 4; oi++) {
#pragma unroll
            for (int g = 0; g < 4; g++) {
                float lo, hi; f2up(acc[oi * 4 + g], lo, hi);
                lo = fmaxf(lo + bb[oi], 0.f); hi = fmaxf(hi + bb[oi], 0.f);
                *(ull*)(s_ht + (o0 + oi) * FS + pg * 8 + g * 2) = f2pk(lo, hi);
            }
        }
    }
    __syncthreads();
    {
        int o0 = (t & 31) * 4, pg = t >> 5;
        ull acc[8];
#pragma unroll
        for (int i = 0; i < 8; i++) acc[i] = 0ull;
#pragma unroll 2
        for (int c = 0; c < 256; c++) {
            float4 w = *(const float4*)(g_csw2t + c * 128 + o0);
            ull w0 = f2pk(w.x, w.x), w1 = f2pk(w.y, w.y);
            ull w2 = f2pk(w.z, w.z), w3 = f2pk(w.w, w.w);
            ulonglong2 v = *(const ulonglong2*)(s_ht + c * FS + pg * 4);
            acc[0] = fma2(w0, v.x, acc[0]); acc[1] = fma2(w0, v.y, acc[1]);
            acc[2] = fma2(w1, v.x, acc[2]); acc[3] = fma2(w1, v.y, acc[3]);
            acc[4] = fma2(w2, v.x, acc[4]); acc[5] = fma2(w2, v.y, acc[5]);
            acc[6] = fma2(w3, v.x, acc[6]); acc[7] = fma2(w3, v.y, acc[7]);
        }
        float4 bq = *(const float4*)(csb2 + o0);
        float bb[4] = { bq.x, bq.y, bq.z, bq.w };
#pragma unroll
        for (int pp = 0; pp < 4; pp++) {
            float4 val;
            float lo, hi;
            f2up(acc[0 + (pp >> 1)], lo, hi); val.x = ((pp & 1) ? hi : lo) + bb[0];
            f2up(acc[2 + (pp >> 1)], lo, hi); val.y = ((pp & 1) ? hi : lo) + bb[1];
            f2up(acc[4 + (pp >> 1)], lo, hi); val.z = ((pp & 1) ? hi : lo) + bb[2];
            f2up(acc[6 + (pp >> 1)], lo, hi); val.w = ((pp & 1) ? hi : lo) + bb[3];
            *(float4*)(g_f2 + (size_t)(base + pg * 4 + pp) * 128 + o0) = val;
        }
    }
}

// ---------------- FPS v3 (R9 measured-best: match-gated index path) -------
__global__ void __launch_bounds__(512, 1) k_fps(const float* __restrict__ x,
                                                float* __restrict__ out_down) {
    extern __shared__ float sp[];
    float* sxx = sp;
    float* syy = sp + NP;
    float* szz = sp + 2 * NP;
    __shared__ unsigned s_bv[2][16];
    __shared__ unsigned s_gi[2];
    int b = blockIdx.x, t = threadIdx.x, lane = t & 31, wid = t >> 5;
    const float* xb = x + (size_t)b * NP * 3;
    for (int i = t; i < NP; i += 512) {
        sxx[i] = xb[3 * i]; syy[i] = xb[3 * i + 1]; szz[i] = xb[3 * i + 2];
    }
    if (t == 0) { s_gi[0] = 0xFFFFFFFFu; s_gi[1] = 0xFFFFFFFFu; }
    __syncthreads();
    float cx = sxx[0], cy = syy[0], cz = szz[0];
    if (t == 0) {
        int o3 = b * MP * 3;
        g_down[o3 + 0] = cx; g_down[o3 + 1] = cy; g_down[o3 + 2] = cz;
        out_down[o3 + 0] = cx; out_down[o3 + 1] = cy; out_down[o3 + 2] = cz;
    }
    int base = t * 16;
    ull pxp[8], pyp[8], pzp[8];
    float md[16];
#pragma unroll
    for (int j = 0; j < 8; j++) {
        pxp[j] = *(const ull*)(sxx + base + 2 * j);
        pyp[j] = *(const ull*)(syy + base + 2 * j);
        pzp[j] = *(const ull*)(szz + base + 2 * j);
        md[2 * j] = 1e10f; md[2 * j + 1] = 1e10f;
    }
    int buf = 0;
    for (int it = 1; it < MP; it++) {
        ull ncx = f2pk(-cx, -cx), ncy = f2pk(-cy, -cy), ncz = f2pk(-cz, -cz);
#pragma unroll
        for (int j = 0; j < 8; j++) {
            ull dx = addx2(pxp[j], ncx);
            ull dy = addx2(pyp[j], ncy);
            ull dz = addx2(pzp[j], ncz);
            ull s = addx2(addx2(mulx2(dx, dx), mulx2(dy, dy)), mulx2(dz, dz));
            float lo, hi; f2up(s, lo, hi);
            md[2 * j]     = fminf(md[2 * j], lo);
            md[2 * j + 1] = fminf(md[2 * j + 1], hi);
        }
        float a0 = fmaxf(md[0], md[1]),  a1 = fmaxf(md[2], md[3]);
        float a2 = fmaxf(md[4], md[5]),  a3 = fmaxf(md[6], md[7]);
        float a4 = fmaxf(md[8], md[9]),  a5 = fmaxf(md[10], md[11]);
        float a6 = fmaxf(md[12], md[13]), a7 = fmaxf(md[14], md[15]);
        float b0 = fmaxf(a0, a1), b1 = fmaxf(a2, a3);
        float b2 = fmaxf(a4, a5), b3 = fmaxf(a6, a7);
        float m = fmaxf(fmaxf(b0, b1), fmaxf(b2, b3));
        unsigned wm = __reduce_max_sync(0xffffffffu, __float_as_uint(m));
        if (lane == 0) s_bv[buf][wid] = wm;
        __syncthreads();
        if (t == 0) s_gi[buf ^ 1] = 0xFFFFFFFFu;   // recycle for next iter
        unsigned gm = __reduce_max_sync(0xffffffffu, s_bv[buf][lane & 15]);
        if (wm == gm) {          // only matching warp(s) pay the index search
            unsigned li = 0xFFFFFFFFu;
#pragma unroll
            for (int j = 15; j >= 0; j--)
                li = (__float_as_uint(md[j]) == gm) ? (unsigned)(base + j) : li;
            unsigned wi = __reduce_min_sync(0xffffffffu, li);
            if (lane == 0) atomicMin(&s_gi[buf], wi);
        }
        __syncthreads();
        unsigned gi = s_gi[buf];
        cx = sxx[gi]; cy = syy[gi]; cz = szz[gi];
        if (t == 0) {
            int o3 = (b * MP + it) * 3;
            g_down[o3 + 0] = cx; g_down[o3 + 1] = cy; g_down[o3 + 2] = cz;
            out_down[o3 + 0] = cx; out_down[o3 + 1] = cy; out_down[o3 + 2] = cz;
        }
        buf ^= 1;
    }
}

// ---------------- KNN v2 (unchanged) ---------------------------------------
__global__ void __launch_bounds__(128) k_knn(const float* __restrict__ x) {
    extern __shared__ float kp[];
    float* sxx = kp;
    float* syy = kp + NP;
    float* szz = kp + 2 * NP;
    float* sdl = kp + 3 * NP;
    int*   sil = (int*)(kp + 3 * NP + 2176);
    int t = threadIdx.x;
    int q = t & 63, half = t >> 6;
    int gid = blockIdx.x * 64 + q;
    int b = gid >> 10;
    const float* xb = x + (size_t)b * NP * 3;
    for (int i = t; i < NP; i += 128) {
        sxx[i] = xb[3 * i]; syy[i] = xb[3 * i + 1]; szz[i] = xb[3 * i + 2];
    }
    __syncthreads();
    float qx = g_down[gid * 3 + 0], qy = g_down[gid * 3 + 1], qz = g_down[gid * 3 + 2];
    float sd = __fadd_rn(__fadd_rn(__fmul_rn(qx, qx), __fmul_rn(qy, qy)), __fmul_rn(qz, qz));
    ull qxp = f2pk(qx, qx), qyp = f2pk(qy, qy), qzp = f2pk(qz, qz);
    ull sdp = f2pk(sd, sd), n2p = f2pk(-2.f, -2.f);
    float dist[17]; int ind[17];
#pragma unroll
    for (int i = 0; i < 17; i++) { dist[i] = 3.4e38f; ind[i] = 0; }
    int n0 = half * 4096;
    for (int n = n0; n < n0 + 4096; n += 2) {
        ull axp = *(const ull*)(sxx + n);
        ull ayp = *(const ull*)(syy + n);
        ull azp = *(const ull*)(szz + n);
        ull sn = addx2(addx2(mulx2(axp, axp), mulx2(ayp, ayp)), mulx2(azp, azp));
        ull dt = addx2(addx2(mulx2(qxp, axp), mulx2(qyp, ayp)), mulx2(qzp, azp));
        ull d2p = addx2(addx2(sdp, sn), mulx2(n2p, dt));
        float dlo, dhi; f2up(d2p, dlo, dhi);
#pragma unroll
        for (int h = 0; h < 2; h++) {
            float d2 = h ? dhi : dlo;
            int ni = n + h;
            if (d2 < dist[16]) {
                int pos = 0;
#pragma unroll
                for (int s = 0; s < 17; s++) pos += (dist[s] <= d2) ? 1 : 0;
#pragma unroll
                for (int s = 16; s > 0; s--) {
                    if (s > pos) { dist[s] = dist[s - 1]; ind[s] = ind[s - 1]; }
                    else if (s == pos) { dist[s] = d2; ind[s] = ni; }
                }
                if (pos == 0) { dist[0] = d2; ind[0] = ni; }
            }
        }
    }
    {
        float* dptr = sdl + (half * 64 + q) * 17;
        int*   iptr = sil + (half * 64 + q) * 17;
#pragma unroll
        for (int s = 0; s < 17; s++) { dptr[s] = dist[s]; iptr[s] = ind[s]; }
    }
    __syncthreads();
    if (t < 64) {
        const float* dA = sdl + q * 17;
        const float* dB = sdl + (64 + q) * 17;
        const int*   iA = sil + q * 17;
        const int*   iB = sil + (64 + q) * 17;
        int ia = 0, ib = 0;
        int* outp = g_knn + (size_t)gid * 17;
#pragma unroll
        for (int k = 0; k < 17; k++) {
            float da = dA[ia], db = dB[ib];
            bool takeA = (da <= db);
            outp[k] = takeA ? iA[ia] : iB[ib];
            ia += takeA ? 1 : 0;
            ib += takeA ? 0 : 1;
        }
    }
}

// ---------------- attention v3: G=4 m's, 512 threads (unchanged) ----------
__global__ void __launch_bounds__(512) k_attn(
    const float* __restrict__ x,
    const float* __restrict__ w3, const float* __restrict__ b3,
    float* __restrict__ out_new)
{
    extern __shared__ __align__(16) float sm[];
    float* feat = sm;
    float* h1i  = sm + 8704;
    float* h2i  = sm + 13056;
    float* fr2  = sm + 17408;
    float* us   = sm + 17920;
    float* zs   = sm + 18944;
    float* knnx = sm + 19456;
    float* dwn  = sm + 19660;
    float* lgA  = sm + 19672;
    float* lgB  = sm + 19736;
    float* lgC  = sm + 19740;
    int*   sidx = (int*)(sm + 19744);

    int t = threadIdx.x;
    int wid = t >> 5, lane = t & 31;
    int bm0 = blockIdx.x * 4;
    int b = bm0 >> 10;
    const float* xb = x + (size_t)b * NP * 3;

    if (t < 68) {
        int id = g_knn[(size_t)bm0 * 17 + t];
        sidx[t] = id;
        knnx[t * 3 + 0] = xb[id * 3 + 0];
        knnx[t * 3 + 1] = xb[id * 3 + 1];
        knnx[t * 3 + 2] = xb[id * 3 + 2];
    }
    if (t < 12) dwn[t] = g_down[(size_t)bm0 * 3 + t];
    __syncthreads();

    for (int r = wid; r < 68; r += 16) {
        const float4* src = (const float4*)(g_f2 + ((size_t)(b * NP) + sidx[r]) * 128);
        ((float4*)(feat + r * 128))[lane] = src[lane];
    }

    for (int i = 0; i < 9; i++) {
        int task = t + 512 * i;
        if (task < 4352) {
            int o = task & 63, row = task >> 6;
            int mi = row / 17;
            int pr = row - 17 * mi;
            int pg = mi >> 1, j = mi & 1;
            const float* kpp = knnx + row * 3;
            const float* dp = dwn + mi * 3;
            float r0 = dp[0], r1 = dp[1], r2v = dp[2];
            float r3 = kpp[0], r4 = kpp[1], r5 = kpp[2];
            const float* w = g_w1f + o * 9;
            float a = g_b1f[o];
            a += w[0] * r0 + w[1] * r1 + w[2] * r2v;
            a += w[3] * r3 + w[4] * r4 + w[5] * r5;
            a += w[6] * (r0 - r3) + w[7] * (r1 - r4) + w[8] * (r2v - r5);
            a = a > 0.f ? a : 0.01f * a;
            h1i[(pg * 17 + pr) * 128 + o * 2 + j] = a;
        }
    }
    __syncthreads();
    {
        const ulonglong2* w2d = (const ulonglong2*)g_s2w2d;
        for (int i = 0; i < 3; i++) {
            int task = t + 512 * i;
            if (task < 1088) {
                int o = task & 31;
                int pr2 = task >> 5;
                int pg = (pr2 >= 17) ? 1 : 0;
                int prow = pr2 - 17 * pg;
                int o2 = o + 32;
                const ulonglong2* hv = (const ulonglong2*)(h1i + (pg * 17 + prow) * 128);
                float ba = g_b2f[o], bb2v = g_b2f[o2];
                ull accA = f2pk(ba, ba), accB = f2pk(bb2v, bb2v);
#pragma unroll 4
                for (int c2 = 0; c2 < 32; c2++) {
                    ulonglong2 v = hv[c2];
                    ulonglong2 wA = w2d[c2 * 64 + o];
                    ulonglong2 wB = w2d[c2 * 64 + o2];
                    accA = fma2(wA.x, v.x, accA); accA = fma2(wA.y, v.y, accA);
                    accB = fma2(wB.x, v.x, accB); accB = fma2(wB.y, v.y, accB);
                }
                float* hrow = h2i + (pg * 17 + prow) * 128;
                float a0, a1; f2up(accA, a0, a1);
                a0 = a0 > 0.f ? a0 : 0.01f * a0;
                a1 = a1 > 0.f ? a1 : 0.01f * a1;
                hrow[o * 2]     = a0;
                hrow[o * 2 + 1] = a1;
                f2up(accB, a0, a1);
                a0 = a0 > 0.f ? a0 : 0.01f * a0;
                a1 = a1 > 0.f ? a1 : 0.01f * a1;
                hrow[o2 * 2]     = a0;
                hrow[o2 * 2 + 1] = a1;
            }
        }
    }
    __syncthreads();
    {
        int mi = t >> 7, o = t & 127;
        int pg = mi >> 1, j = mi & 1;
        const ulonglong2* hc2 = (const ulonglong2*)(h2i + pg * 17 * 128);
        float acc = b3[o];
#pragma unroll 4
        for (int c4 = 0; c4 < 16; c4++) {
            float4 w = ((const float4*)g_s2w3p)[c4 * 128 + o];
            ulonglong2 p0 = hc2[2 * c4], p1 = hc2[2 * c4 + 1];
            float l0, h0v, l1, h1v, l2, h2v, l3, h3v;
            f2up(p0.x, l0, h0v); f2up(p0.y, l1, h1v);
            f2up(p1.x, l2, h2v); f2up(p1.y, l3, h3v);
            float v0 = j ? h0v : l0, v1 = j ? h1v : l1;
            float v2 = j ? h2v : l2, v3 = j ? h3v : l3;
            acc += w.x * v0 + w.y * v1 + w.z * v2 + w.w * v3;
        }
        fr2[mi * 128 + o] = acc;
    }
    __syncthreads();
    {
        int ch = t & 255, grp = t >> 8;
        int m0 = grp * 2, m1 = grp * 2 + 1;
        const float4* ap = (const float4*)g_Ap;
        float a0 = 0.f, a1 = 0.f;
        for (int c4 = 0; c4 < 32; c4++) {
            float4 w = ap[c4 * 256 + ch];
            float4 v0 = *(const float4*)(feat + m0 * 17 * 128 + c4 * 4);
            float4 v1 = *(const float4*)(feat + m1 * 17 * 128 + c4 * 4);
            a0 += w.x * v0.x + w.y * v0.y + w.z * v0.z + w.w * v0.w;
            a1 += w.x * v1.x + w.y * v1.y + w.z * v1.z + w.w * v1.w;
        }
        for (int c4 = 0; c4 < 32; c4++) {
            float4 w = ap[(32 + c4) * 256 + ch];
            float4 v0 = *(const float4*)(fr2 + m0 * 128 + c4 * 4);
            float4 v1 = *(const float4*)(fr2 + m1 * 128 + c4 * 4);
            a0 += w.x * v0.x + w.y * v0.y + w.z * v0.z + w.w * v0.w;
            a1 += w.x * v1.x + w.y * v1.y + w.z * v1.z + w.w * v1.w;
        }
        float cv = g_cvec[ch];
        us[m0 * 256 + ch] = a0 + cv;
        us[m1 * 256 + ch] = a1 + cv;
    }
    __syncthreads();
    {
        int mi = t >> 7, rem = t & 127, c = rem >> 1, oh = rem & 1;
        const float* ur = us + mi * 256 + 128 + oh * 64;
        float acc = 0.f;
#pragma unroll 4
        for (int o = 0; o < 64; o++) acc += __ldg(w3 + (oh * 64 + o) * 64 + c) * ur[o];
        zs[(mi * 64 + c) * 2 + oh] = acc;
    }
    __syncthreads();
    for (int task = wid; task < 72; task += 16) {
        float s = 0.f;
        if (task < 64) {
            int mi = task >> 4, j = task & 15;
            const float* uf = us + mi * 256;
            const float* fr = feat + (mi * 17 + 1 + j) * 128;
#pragma unroll
            for (int k = 0; k < 4; k++) { int o = lane + 32 * k; s += uf[o] * fr[o]; }
            const float* hj = h2i + ((mi >> 1) * 17 + 1 + j) * 128;
#pragma unroll
            for (int k = 0; k < 2; k++) {
                int c = lane + 32 * k;
                s += (zs[(mi * 64 + c) * 2] + zs[(mi * 64 + c) * 2 + 1]) * hj[c * 2 + (mi & 1)];
            }
        } else if (task < 68) {
            int mi = task - 64;
            const float* fl = feat + mi * 17 * 128;
            const float* fh = fr2 + mi * 128;
#pragma unroll
            for (int k = 0; k < 4; k++) {
                int o = lane + 32 * k;
                s += __ldg(&g_vb[o]) * fl[o] + __ldg(&g_vb[128 + o]) * fh[o];
            }
        } else {
            int mi = task - 68;
            const float* uh = us + mi * 256 + 128;
#pragma unroll
            for (int k = 0; k < 4; k++) { int o = lane + 32 * k; s += uh[o] * __ldg(b3 + o); }
        }
#pragma unroll
        for (int off = 16; off; off >>= 1) s += __shfl_down_sync(0xffffffffu, s, off);
        if (lane == 0) {
            if (task < 64) lgA[task] = s;
            else if (task < 68) lgB[task - 64] = s;
            else lgC[task - 68] = s;
        }
    }
    __syncthreads();

    if (t < 4) {
        float ex = lgB[t] + lgC[t] + g_s0[0];
        float l[16], mx = -3.4e38f;
#pragma unroll
        for (int j = 0; j < 16; j++) { l[j] = lgA[t * 16 + j] + ex; mx = fmaxf(mx, l[j]); }
        float sum = 0.f;
#pragma unroll
        for (int j = 0; j < 16; j++) { l[j] = expf(l[j] - mx); sum += l[j]; }
        float inv = 1.f / sum;
        float nx = 0.f, ny = 0.f, nz = 0.f;
#pragma unroll
        for (int j = 0; j < 16; j++) {
            float w = l[j] * inv;
            const float* kpp = knnx + (t * 17 + 1 + j) * 3;
            nx += w * kpp[0]; ny += w * kpp[1]; nz += w * kpp[2];
        }
        float* po = out_new + (size_t)(bm0 + t) * 3;
        po[0] = nx; po[1] = ny; po[2] = nz;
    }
}

// ---------------- launch ---------------------------------------------------
extern "C" void kernel_launch(void* const* d_in, const int* in_sizes, int n_in,
                              void* d_out, int out_size) {
    const float* x      = (const float*)d_in[0];
    const float* gf     = (const float*)d_in[1];
    const float* c1_w1  = (const float*)d_in[2];
    const float* c1_b1  = (const float*)d_in[3];
    const float* c1_w2  = (const float*)d_in[4];
    const float* c1_b2  = (const float*)d_in[5];
    const float* cf_w1  = (const float*)d_in[6];
    const float* cf_b1  = (const float*)d_in[7];
    const float* cf_w2  = (const float*)d_in[8];
    const float* cf_b2  = (const float*)d_in[9];
    const float* cs_w1  = (const float*)d_in[10];
    const float* cs_b1  = (const float*)d_in[11];
    const float* cs_w2  = (const float*)d_in[12];
    const float* cs_b2  = (const float*)d_in[13];
    const float* s2_w1  = (const float*)d_in[14];
    const float* s2_b1  = (const float*)d_in[15];
    const float* s2_g1  = (const float*)d_in[16];
    const float* s2_bb1 = (const float*)d_in[17];
    const float* s2_w2  = (const float*)d_in[18];
    const float* s2_b2  = (const float*)d_in[19];
    const float* s2_g2  = (const float*)d_in[20];
    const float* s2_bb2 = (const float*)d_in[21];
    const float* s2_w3  = (const float*)d_in[22];
    const float* s2_b3  = (const float*)d_in[23];
    const float* q_w    = (const float*)d_in[24];
    const float* q_b    = (const float*)d_in[25];
    const float* k_w    = (const float*)d_in[26];
    const float* k_b    = (const float*)d_in[27];
    float* out = (float*)d_out;

    static bool s_init = false;
    static cudaStream_t st;
    static cudaEvent_t evF, evD;
    const int FEAT_SMEM = (384 * FS + 96) * 4;
    const int ATTN_SMEM = 19812 * 4;
    const int KNN_SMEM  = (3 * NP + 2 * 2176) * 4;
    if (!s_init) {
        cudaStreamCreateWithFlags(&st, cudaStreamNonBlocking);
        cudaEventCreateWithFlags(&evF, cudaEventDisableTiming);
        cudaEventCreateWithFlags(&evD, cudaEventDisableTiming);
        cudaFuncSetAttribute(k_feat, cudaFuncAttributeMaxDynamicSharedMemorySize, FEAT_SMEM);
        cudaFuncSetAttribute(k_knn,  cudaFuncAttributeMaxDynamicSharedMemorySize, KNN_SMEM);
        cudaFuncSetAttribute(k_fps,  cudaFuncAttributeMaxDynamicSharedMemorySize, NP * 3 * 4);
        cudaFuncSetAttribute(k_attn, cudaFuncAttributeMaxDynamicSharedMemorySize, ATTN_SMEM);
        s_init = true;
    }

    // fork point; side chain submitted FIRST so fps's 8 blocks become resident
    // before prep/feat flood every SM with high-smem blocks.
    cudaEventRecord(evF, 0);
    cudaStreamWaitEvent(st, evF, 0);
    k_fps<<<BN, 512, NP * 3 * 4, st>>>(x, out);                       // #1
    k_prep<<<730, 256>>>(cs_w1, cs_w2, c1_w2,                         // #2
                         s2_w1, s2_b1, s2_g1, s2_bb1,
                         s2_w2, s2_b2, s2_g2, s2_bb2, s2_w3,
                         q_w, k_w, q_b, k_b,
                         gf, cf_w1, cf_b1, cf_w2, cf_b2);
    k_prep2<<<BN, 256>>>(cs_b1);                                      // #3
    k_knn<<<(BN * MP) / 64, 128, KNN_SMEM, st>>>(x);                  // #4 <- profiled
    k_feat<<<(BN * NP) / 32, 256, FEAT_SMEM>>>(x,                     // #5
        c1_w1, c1_b1, c1_b2, cs_b2);
    cudaEventRecord(evD, st);
    cudaStreamWaitEvent(0, evD, 0);
    k_attn<<<(BN * MP) / 4, 512, ATTN_SMEM>>>(x, s2_w3, s2_b3,        // #6
        out + (size_t)BN * MP * 3);
}

// round 13
// speedup vs baseline: 1.0816x; 1.0559x over previous
#include <cuda_runtime.h>
#include <math.h>

#define BN 8
#define NP 8192
#define MP 1024
#define KNB 17
#define FS 36

typedef unsigned long long ull;

// ---------------- scratch ----------------
__device__ float g_gvec[BN * 128];
__device__ float g_f2[BN * NP * 128];
__device__ float g_down[BN * MP * 3];
__device__ int   g_knn[BN * MP * KNB];
__device__ float g_csw1t[256 * 256];
__device__ float g_csw2t[256 * 128];
__device__ float g_c1w2t[64 * 128];
__device__ float g_hg[BN * 256];
__device__ ull   g_s2w2d[64 * 64];
__device__ float g_s2w3p[128 * 64];
__device__ float g_w1f[64 * 9];
__device__ float g_b1f[64];
__device__ float g_b2f[64];
__device__ float g_Ap[256 * 256];
__device__ float g_cvec[256];
__device__ float g_vb[256];
__device__ float g_s0[1];

__device__ __forceinline__ ull f2pk(float lo, float hi) {
    ull r; asm("mov.b64 %0,{%1,%2};" : "=l"(r) : "f"(lo), "f"(hi)); return r;
}
__device__ __forceinline__ void f2up(ull v, float& lo, float& hi) {
    asm("mov.b64 {%0,%1},%2;" : "=f"(lo), "=f"(hi) : "l"(v));
}
__device__ __forceinline__ ull addx2(ull a, ull b) {
    ull r; asm("add.rn.f32x2 %0,%1,%2;" : "=l"(r) : "l"(a), "l"(b)); return r;
}
__device__ __forceinline__ ull mulx2(ull a, ull b) {
    ull r; asm("mul.rn.f32x2 %0,%1,%2;" : "=l"(r) : "l"(a), "l"(b)); return r;
}
__device__ __forceinline__ ull fma2(ull a, ull b, ull c) {
    ull r; asm("fma.rn.f32x2 %0,%1,%2,%3;" : "=l"(r) : "l"(a), "l"(b), "l"(c)); return r;
}

// ---------------- prep ----------------------------------------------------
__device__ __forceinline__ void rp_t(const float* __restrict__ w, float* __restrict__ o,
                                     int O, int C, int blk) {
    int g = blk * 256 + threadIdx.x;
    if (g >= O * C) return;
    int c = g / O, oo = g - c * O;
    o[c * O + oo] = w[oo * C + c];
}

__global__ void k_prep(const float* __restrict__ cs_w1, const float* __restrict__ cs_w2,
                       const float* __restrict__ c1_w2,
                       const float* __restrict__ s2_w1, const float* __restrict__ s2_b1,
                       const float* __restrict__ s2_g1, const float* __restrict__ s2_bb1,
                       const float* __restrict__ s2_w2, const float* __restrict__ s2_b2,
                       const float* __restrict__ s2_g2, const float* __restrict__ s2_bb2,
                       const float* __restrict__ s2_w3,
                       const float* __restrict__ q_w, const float* __restrict__ k_w,
                       const float* __restrict__ q_b, const float* __restrict__ k_b,
                       const float* __restrict__ gf,
                       const float* __restrict__ cf_w1, const float* __restrict__ cf_b1,
                       const float* __restrict__ cf_w2, const float* __restrict__ cf_b2) {
    __shared__ float s_buf[512];
    __shared__ float s_h[256];
    __shared__ float s_red[8];
    const float bnc = 1.f / sqrtf(1.0f + 1e-5f);
    int blk = blockIdx.x, t = threadIdx.x;
    if (blk < 256)  { rp_t(cs_w1, g_csw1t, 256, 256, blk); return; }
    if (blk < 384)  { rp_t(cs_w2, g_csw2t, 128, 256, blk - 256); return; }
    if (blk < 416)  { rp_t(c1_w2, g_c1w2t, 128, 64, blk - 384); return; }
    if (blk < 432) {
        int g = (blk - 416) * 256 + t;
        int j = g & 1, o = (g >> 1) & 63, c2 = g >> 7;
        float v = s2_w2[o * 64 + 2 * c2 + j] * (s2_g2[o] * bnc);
        g_s2w2d[g] = f2pk(v, v);
        return;
    }
    if (blk < 464) {
        int g = (blk - 432) * 256 + t;
        int o = g >> 6, c = g & 63;
        g_s2w3p[((c >> 2) * 128 + o) * 4 + (c & 3)] = s2_w3[o * 64 + c];
        return;
    }
    if (blk < 720) {
        int i = blk - 464;
        s_buf[t] = k_w[t * 256 + i];
        __syncthreads();
        float acc = 0.f;
        for (int o = 0; o < 256; o++) acc += s_buf[o] * __ldg(q_w + o * 256 + t);
        g_Ap[((t >> 2) * 256 + i) * 4 + (t & 3)] = acc;
        float part = s_buf[t] * q_b[t];
#pragma unroll
        for (int off = 16; off; off >>= 1) part += __shfl_down_sync(0xffffffffu, part, off);
        if ((t & 31) == 0) s_red[t >> 5] = part;
        __syncthreads();
        if (t == 0) { float s = 0.f; for (int w = 0; w < 8; w++) s += s_red[w]; g_cvec[i] = s; }
        return;
    }
    if (blk < 728) {
        int b = blk - 720;
        for (int i = t; i < 512; i += 256) s_buf[i] = gf[b * 512 + i];
        __syncthreads();
        float a = cf_b1[t];
        const float* wr = cf_w1 + t * 512;
        for (int c = 0; c < 512; c++) a += wr[c] * s_buf[c];
        s_h[t] = fmaxf(a, 0.f);
        __syncthreads();
        if (t < 128) {
            float a2 = cf_b2[t];
            const float* w2r = cf_w2 + t * 256;
            for (int c = 0; c < 256; c++) a2 += w2r[c] * s_h[c];
            g_gvec[b * 128 + t] = a2;
        }
        return;
    }
    if (blk == 728) {
        float acc = 0.f;
        for (int o = 0; o < 256; o++) acc += __ldg(q_w + o * 256 + t) * k_b[o];
        g_vb[t] = acc;
        if (t == 0) {
            float s = 0.f;
            for (int o = 0; o < 256; o++) s += q_b[o] * k_b[o];
            g_s0[0] = s;
        }
        return;
    }
    for (int i = t; i < 576; i += 256) {
        int o = i / 9;
        g_w1f[i] = s2_w1[i] * (s2_g1[o] * bnc);
    }
    if (t < 64) {
        g_b1f[t] = s2_b1[t] * (s2_g1[t] * bnc) + s2_bb1[t];
        g_b2f[t] = s2_b2[t] * (s2_g2[t] * bnc) + s2_bb2[t];
    }
}

__global__ void k_prep2(const float* __restrict__ csb1) {
    __shared__ float gv[128];
    int b = blockIdx.x, t = threadIdx.x;
    if (t < 128) gv[t] = g_gvec[b * 128 + t];
    __syncthreads();
    float acc = csb1[t];
    for (int c = 0; c < 128; c++) acc += g_csw1t[(128 + c) * 256 + t] * gv[c];
    g_hg[b * 256 + t] = acc;
}

// ---------------- fused c1 + cs MLP (unchanged) ---------------------------
__global__ void __launch_bounds__(256) k_feat(const float* __restrict__ x,
                                              const float* __restrict__ c1w1,
                                              const float* __restrict__ c1b1,
                                              const float* __restrict__ c1b2,
                                              const float* __restrict__ csb2) {
    extern __shared__ __align__(16) float fm[];
    float* s_int = fm;
    float* s_ht  = fm + 128 * FS;
    float* s_h64 = s_ht;
    float* s_xyz = fm + 384 * FS;
    int t = threadIdx.x;
    int base = blockIdx.x * 32;
    int b = base >> 13;
    if (t < 96) s_xyz[t] = x[(size_t)base * 3 + t];
    __syncthreads();
    for (int i = 0; i < 8; i++) {
        int task = t + 256 * i;
        int p = task & 31, o = task >> 5;
        float a = c1b1[o];
        a += c1w1[o * 3 + 0] * s_xyz[p * 3 + 0];
        a += c1w1[o * 3 + 1] * s_xyz[p * 3 + 1];
        a += c1w1[o * 3 + 2] * s_xyz[p * 3 + 2];
        s_h64[o * FS + p] = fmaxf(a, 0.f);
    }
    __syncthreads();
    {
        int o0 = (t & 31) * 4, pg = t >> 5;
        ull acc[8];
#pragma unroll
        for (int i = 0; i < 8; i++) acc[i] = 0ull;
#pragma unroll 4
        for (int c = 0; c < 64; c++) {
            float4 w = *(const float4*)(g_c1w2t + c * 128 + o0);
            ull w0 = f2pk(w.x, w.x), w1 = f2pk(w.y, w.y);
            ull w2 = f2pk(w.z, w.z), w3 = f2pk(w.w, w.w);
            ulonglong2 v = *(const ulonglong2*)(s_h64 + c * FS + pg * 4);
            acc[0] = fma2(w0, v.x, acc[0]); acc[1] = fma2(w0, v.y, acc[1]);
            acc[2] = fma2(w1, v.x, acc[2]); acc[3] = fma2(w1, v.y, acc[3]);
            acc[4] = fma2(w2, v.x, acc[4]); acc[5] = fma2(w2, v.y, acc[5]);
            acc[6] = fma2(w3, v.x, acc[6]); acc[7] = fma2(w3, v.y, acc[7]);
        }
        float4 bq = *(const float4*)(c1b2 + o0);
        float bb[4] = { bq.x, bq.y, bq.z, bq.w };
        __syncthreads();
#pragma unroll
        for (int oi = 0; oi < 4; oi++) {
            ull bp = f2pk(bb[oi], bb[oi]);
            *(ull*)(s_int + (o0 + oi) * FS + pg * 4)     = addx2(acc[oi * 2], bp);
            *(ull*)(s_int + (o0 + oi) * FS + pg * 4 + 2) = addx2(acc[oi * 2 + 1], bp);
        }
    }
    __syncthreads();
    {
        int o0 = (t & 63) * 4, pg = t >> 6;
        ull acc[16];
#pragma unroll
        for (int i = 0; i < 16; i++) acc[i] = 0ull;
#pragma unroll 2
        for (int c = 0; c < 128; c++) {
            float4 w = *(const float4*)(g_csw1t + c * 256 + o0);
            ull w0 = f2pk(w.x, w.x), w1 = f2pk(w.y, w.y);
            ull w2 = f2pk(w.z, w.z), w3 = f2pk(w.w, w.w);
            ulonglong2 v01 = *(const ulonglong2*)(s_int + c * FS + pg * 8);
            ulonglong2 v23 = *(const ulonglong2*)(s_int + c * FS + pg * 8 + 4);
            acc[0]  = fma2(w0, v01.x, acc[0]);  acc[1]  = fma2(w0, v01.y, acc[1]);
            acc[2]  = fma2(w0, v23.x, acc[2]);  acc[3]  = fma2(w0, v23.y, acc[3]);
            acc[4]  = fma2(w1, v01.x, acc[4]);  acc[5]  = fma2(w1, v01.y, acc[5]);
            acc[6]  = fma2(w1, v23.x, acc[6]);  acc[7]  = fma2(w1, v23.y, acc[7]);
            acc[8]  = fma2(w2, v01.x, acc[8]);  acc[9]  = fma2(w2, v01.y, acc[9]);
            acc[10] = fma2(w2, v23.x, acc[10]); acc[11] = fma2(w2, v23.y, acc[11]);
            acc[12] = fma2(w3, v01.x, acc[12]); acc[13] = fma2(w3, v01.y, acc[13]);
            acc[14] = fma2(w3, v23.x, acc[14]); acc[15] = fma2(w3, v23.y, acc[15]);
        }
        float4 bq = *(const float4*)(g_hg + b * 256 + o0);
        float bb[4] = { bq.x, bq.y, bq.z, bq.w };
        __syncthreads();
#pragma unroll
        for (int oi = 0; oi < 4; oi++) {
#pragma unroll
            for (int g = 0; g < 4; g++) {
                float lo, hi; f2up(acc[oi * 4 + g], lo, hi);
                lo = fmaxf(lo + bb[oi], 0.f); hi = fmaxf(hi + bb[oi], 0.f);
                *(ull*)(s_ht + (o0 + oi) * FS + pg * 8 + g * 2) = f2pk(lo, hi);
            }
        }
    }
    __syncthreads();
    {
        int o0 = (t & 31) * 4, pg = t >> 5;
        ull acc[8];
#pragma unroll
        for (int i = 0; i < 8; i++) acc[i] = 0ull;
#pragma unroll 2
        for (int c = 0; c < 256; c++) {
            float4 w = *(const float4*)(g_csw2t + c * 128 + o0);
            ull w0 = f2pk(w.x, w.x), w1 = f2pk(w.y, w.y);
            ull w2 = f2pk(w.z, w.z), w3 = f2pk(w.w, w.w);
            ulonglong2 v = *(const ulonglong2*)(s_ht + c * FS + pg * 4);
            acc[0] = fma2(w0, v.x, acc[0]); acc[1] = fma2(w0, v.y, acc[1]);
            acc[2] = fma2(w1, v.x, acc[2]); acc[3] = fma2(w1, v.y, acc[3]);
            acc[4] = fma2(w2, v.x, acc[4]); acc[5] = fma2(w2, v.y, acc[5]);
            acc[6] = fma2(w3, v.x, acc[6]); acc[7] = fma2(w3, v.y, acc[7]);
        }
        float4 bq = *(const float4*)(csb2 + o0);
        float bb[4] = { bq.x, bq.y, bq.z, bq.w };
#pragma unroll
        for (int pp = 0; pp < 4; pp++) {
            float4 val;
            float lo, hi;
            f2up(acc[0 + (pp >> 1)], lo, hi); val.x = ((pp & 1) ? hi : lo) + bb[0];
            f2up(acc[2 + (pp >> 1)], lo, hi); val.y = ((pp & 1) ? hi : lo) + bb[1];
            f2up(acc[4 + (pp >> 1)], lo, hi); val.z = ((pp & 1) ? hi : lo) + bb[2];
            f2up(acc[6 + (pp >> 1)], lo, hi); val.w = ((pp & 1) ? hi : lo) + bb[3];
            *(float4*)(g_f2 + (size_t)(base + pg * 4 + pp) * 128 + o0) = val;
        }
    }
}

// ---------------- FPS v3 (measured-best, unchanged) -----------------------
__global__ void __launch_bounds__(512, 1) k_fps(const float* __restrict__ x,
                                                float* __restrict__ out_down) {
    extern __shared__ float sp[];
    float* sxx = sp;
    float* syy = sp + NP;
    float* szz = sp + 2 * NP;
    __shared__ unsigned s_bv[2][16];
    __shared__ unsigned s_gi[2];
    int b = blockIdx.x, t = threadIdx.x, lane = t & 31, wid = t >> 5;
    const float* xb = x + (size_t)b * NP * 3;
    for (int i = t; i < NP; i += 512) {
        sxx[i] = xb[3 * i]; syy[i] = xb[3 * i + 1]; szz[i] = xb[3 * i + 2];
    }
    if (t == 0) { s_gi[0] = 0xFFFFFFFFu; s_gi[1] = 0xFFFFFFFFu; }
    __syncthreads();
    float cx = sxx[0], cy = syy[0], cz = szz[0];
    if (t == 0) {
        int o3 = b * MP * 3;
        g_down[o3 + 0] = cx; g_down[o3 + 1] = cy; g_down[o3 + 2] = cz;
        out_down[o3 + 0] = cx; out_down[o3 + 1] = cy; out_down[o3 + 2] = cz;
    }
    int base = t * 16;
    ull pxp[8], pyp[8], pzp[8];
    float md[16];
#pragma unroll
    for (int j = 0; j < 8; j++) {
        pxp[j] = *(const ull*)(sxx + base + 2 * j);
        pyp[j] = *(const ull*)(syy + base + 2 * j);
        pzp[j] = *(const ull*)(szz + base + 2 * j);
        md[2 * j] = 1e10f; md[2 * j + 1] = 1e10f;
    }
    int buf = 0;
    for (int it = 1; it < MP; it++) {
        ull ncx = f2pk(-cx, -cx), ncy = f2pk(-cy, -cy), ncz = f2pk(-cz, -cz);
#pragma unroll
        for (int j = 0; j < 8; j++) {
            ull dx = addx2(pxp[j], ncx);
            ull dy = addx2(pyp[j], ncy);
            ull dz = addx2(pzp[j], ncz);
            ull s = addx2(addx2(mulx2(dx, dx), mulx2(dy, dy)), mulx2(dz, dz));
            float lo, hi; f2up(s, lo, hi);
            md[2 * j]     = fminf(md[2 * j], lo);
            md[2 * j + 1] = fminf(md[2 * j + 1], hi);
        }
        float a0 = fmaxf(md[0], md[1]),  a1 = fmaxf(md[2], md[3]);
        float a2 = fmaxf(md[4], md[5]),  a3 = fmaxf(md[6], md[7]);
        float a4 = fmaxf(md[8], md[9]),  a5 = fmaxf(md[10], md[11]);
        float a6 = fmaxf(md[12], md[13]), a7 = fmaxf(md[14], md[15]);
        float b0 = fmaxf(a0, a1), b1 = fmaxf(a2, a3);
        float b2 = fmaxf(a4, a5), b3 = fmaxf(a6, a7);
        float m = fmaxf(fmaxf(b0, b1), fmaxf(b2, b3));
        unsigned wm = __reduce_max_sync(0xffffffffu, __float_as_uint(m));
        if (lane == 0) s_bv[buf][wid] = wm;
        __syncthreads();
        if (t == 0) s_gi[buf ^ 1] = 0xFFFFFFFFu;
        unsigned gm = __reduce_max_sync(0xffffffffu, s_bv[buf][lane & 15]);
        if (wm == gm) {
            unsigned li = 0xFFFFFFFFu;
#pragma unroll
            for (int j = 15; j >= 0; j--)
                li = (__float_as_uint(md[j]) == gm) ? (unsigned)(base + j) : li;
            unsigned wi = __reduce_min_sync(0xffffffffu, li);
            if (lane == 0) atomicMin(&s_gi[buf], wi);
        }
        __syncthreads();
        unsigned gi = s_gi[buf];
        cx = sxx[gi]; cy = syy[gi]; cz = szz[gi];
        if (t == 0) {
            int o3 = (b * MP + it) * 3;
            g_down[o3 + 0] = cx; g_down[o3 + 1] = cy; g_down[o3 + 2] = cz;
            out_down[o3 + 0] = cx; out_down[o3 + 1] = cy; out_down[o3 + 2] = cz;
        }
        buf ^= 1;
    }
}

// ---------------- KNN v3: 512 thr, split-8, 3-stage stable merge ----------
__device__ __forceinline__ void merge17(const float* __restrict__ dA, const int* __restrict__ iA,
                                        const float* __restrict__ dB, const int* __restrict__ iB,
                                        float* __restrict__ dO, int* __restrict__ iO) {
    int ia = 0, ib = 0;
#pragma unroll
    for (int k = 0; k < 17; k++) {
        float da = dA[ia], db = dB[ib];
        bool tA = (da <= db);           // A = lower indices wins ties (lax.top_k stable)
        dO[k] = tA ? da : db;
        iO[k] = tA ? iA[ia] : iB[ib];
        ia += tA ? 1 : 0;
        ib += tA ? 0 : 1;
    }
}

__global__ void __launch_bounds__(512) k_knn(const float* __restrict__ x) {
    extern __shared__ float kp[];
    float* sxx = kp;
    float* syy = kp + NP;
    float* szz = kp + 2 * NP;
    float* sdl = kp + 3 * NP;                       // [8*64*17] floats (stage-2 reuses)
    int*   sil = (int*)(kp + 3 * NP + 8704);        // [8*64*17] ints
    float* t1d = kp + 3 * NP + 17408;               // [4*64*17]
    int*   t1i = (int*)(kp + 3 * NP + 21760);       // [4*64*17]
    int t = threadIdx.x;
    int q = t & 63, split = t >> 6;                 // 8 splits x 64 queries
    int gid = blockIdx.x * 64 + q;
    int b = gid >> 10;
    const float* xb = x + (size_t)b * NP * 3;
    for (int i = t; i < NP; i += 512) {
        sxx[i] = xb[3 * i]; syy[i] = xb[3 * i + 1]; szz[i] = xb[3 * i + 2];
    }
    __syncthreads();
    float qx = g_down[gid * 3 + 0], qy = g_down[gid * 3 + 1], qz = g_down[gid * 3 + 2];
    float sd = __fadd_rn(__fadd_rn(__fmul_rn(qx, qx), __fmul_rn(qy, qy)), __fmul_rn(qz, qz));
    ull qxp = f2pk(qx, qx), qyp = f2pk(qy, qy), qzp = f2pk(qz, qz);
    ull sdp = f2pk(sd, sd), n2p = f2pk(-2.f, -2.f);
    float dist[17]; int ind[17];
#pragma unroll
    for (int i = 0; i < 17; i++) { dist[i] = 3.4e38f; ind[i] = 0; }
    int n0 = split * 1024;
    for (int n = n0; n < n0 + 1024; n += 2) {
        ull axp = *(const ull*)(sxx + n);
        ull ayp = *(const ull*)(syy + n);
        ull azp = *(const ull*)(szz + n);
        ull sn = addx2(addx2(mulx2(axp, axp), mulx2(ayp, ayp)), mulx2(azp, azp));
        ull dt = addx2(addx2(mulx2(qxp, axp), mulx2(qyp, ayp)), mulx2(qzp, azp));
        ull d2p = addx2(addx2(sdp, sn), mulx2(n2p, dt));
        float dlo, dhi; f2up(d2p, dlo, dhi);
#pragma unroll
        for (int h = 0; h < 2; h++) {
            float d2 = h ? dhi : dlo;
            int ni = n + h;
            if (d2 < dist[16]) {
                int pos = 0;
#pragma unroll
                for (int s = 0; s < 17; s++) pos += (dist[s] <= d2) ? 1 : 0;
#pragma unroll
                for (int s = 16; s > 0; s--) {
                    if (s > pos) { dist[s] = dist[s - 1]; ind[s] = ind[s - 1]; }
                    else if (s == pos) { dist[s] = d2; ind[s] = ni; }
                }
                if (pos == 0) { dist[0] = d2; ind[0] = ni; }
            }
        }
    }
    {
        float* dptr = sdl + (split * 64 + q) * 17;
        int*   iptr = sil + (split * 64 + q) * 17;
#pragma unroll
        for (int s = 0; s < 17; s++) { dptr[s] = dist[s]; iptr[s] = ind[s]; }
    }
    __syncthreads();
    // stage 1: 8 lists -> 4 (256 threads)
    if (t < 256) {
        int p = t >> 6, qq = t & 63;
        int la = (2 * p) * 64 + qq, lb = (2 * p + 1) * 64 + qq;
        merge17(sdl + la * 17, sil + la * 17, sdl + lb * 17, sil + lb * 17,
                t1d + (p * 64 + qq) * 17, t1i + (p * 64 + qq) * 17);
    }
    __syncthreads();
    // stage 2: 4 -> 2 (128 threads), write into reused sdl/sil region
    if (t < 128) {
        int p = t >> 6, qq = t & 63;
        int la = (2 * p) * 64 + qq, lb = (2 * p + 1) * 64 + qq;
        merge17(t1d + la * 17, t1i + la * 17, t1d + lb * 17, t1i + lb * 17,
                sdl + (p * 64 + qq) * 17, sil + (p * 64 + qq) * 17);
    }
    __syncthreads();
    // stage 3: 2 -> 1 (64 threads), indices only to gmem
    if (t < 64) {
        const float* dA = sdl + t * 17;
        const float* dB = sdl + (64 + t) * 17;
        const int*   iA = sil + t * 17;
        const int*   iB = sil + (64 + t) * 17;
        int ia = 0, ib = 0;
        int* outp = g_knn + (size_t)(blockIdx.x * 64 + t) * 17;
#pragma unroll
        for (int k = 0; k < 17; k++) {
            float da = dA[ia], db = dB[ib];
            bool tA = (da <= db);
            outp[k] = tA ? iA[ia] : iB[ib];
            ia += tA ? 1 : 0;
            ib += tA ? 0 : 1;
        }
    }
}

// ---------------- attention v3 (unchanged) ---------------------------------
__global__ void __launch_bounds__(512) k_attn(
    const float* __restrict__ x,
    const float* __restrict__ w3, const float* __restrict__ b3,
    float* __restrict__ out_new)
{
    extern __shared__ __align__(16) float sm[];
    float* feat = sm;
    float* h1i  = sm + 8704;
    float* h2i  = sm + 13056;
    float* fr2  = sm + 17408;
    float* us   = sm + 17920;
    float* zs   = sm + 18944;
    float* knnx = sm + 19456;
    float* dwn  = sm + 19660;
    float* lgA  = sm + 19672;
    float* lgB  = sm + 19736;
    float* lgC  = sm + 19740;
    int*   sidx = (int*)(sm + 19744);

    int t = threadIdx.x;
    int wid = t >> 5, lane = t & 31;
    int bm0 = blockIdx.x * 4;
    int b = bm0 >> 10;
    const float* xb = x + (size_t)b * NP * 3;

    if (t < 68) {
        int id = g_knn[(size_t)bm0 * 17 + t];
        sidx[t] = id;
        knnx[t * 3 + 0] = xb[id * 3 + 0];
        knnx[t * 3 + 1] = xb[id * 3 + 1];
        knnx[t * 3 + 2] = xb[id * 3 + 2];
    }
    if (t < 12) dwn[t] = g_down[(size_t)bm0 * 3 + t];
    __syncthreads();

    for (int r = wid; r < 68; r += 16) {
        const float4* src = (const float4*)(g_f2 + ((size_t)(b * NP) + sidx[r]) * 128);
        ((float4*)(feat + r * 128))[lane] = src[lane];
    }

    for (int i = 0; i < 9; i++) {
        int task = t + 512 * i;
        if (task < 4352) {
            int o = task & 63, row = task >> 6;
            int mi = row / 17;
            int pr = row - 17 * mi;
            int pg = mi >> 1, j = mi & 1;
            const float* kpp = knnx + row * 3;
            const float* dp = dwn + mi * 3;
            float r0 = dp[0], r1 = dp[1], r2v = dp[2];
            float r3 = kpp[0], r4 = kpp[1], r5 = kpp[2];
            const float* w = g_w1f + o * 9;
            float a = g_b1f[o];
            a += w[0] * r0 + w[1] * r1 + w[2] * r2v;
            a += w[3] * r3 + w[4] * r4 + w[5] * r5;
            a += w[6] * (r0 - r3) + w[7] * (r1 - r4) + w[8] * (r2v - r5);
            a = a > 0.f ? a : 0.01f * a;
            h1i[(pg * 17 + pr) * 128 + o * 2 + j] = a;
        }
    }
    __syncthreads();
    {
        const ulonglong2* w2d = (const ulonglong2*)g_s2w2d;
        for (int i = 0; i < 3; i++) {
            int task = t + 512 * i;
            if (task < 1088) {
                int o = task & 31;
                int pr2 = task >> 5;
                int pg = (pr2 >= 17) ? 1 : 0;
                int prow = pr2 - 17 * pg;
                int o2 = o + 32;
                const ulonglong2* hv = (const ulonglong2*)(h1i + (pg * 17 + prow) * 128);
                float ba = g_b2f[o], bb2v = g_b2f[o2];
                ull accA = f2pk(ba, ba), accB = f2pk(bb2v, bb2v);
#pragma unroll 4
                for (int c2 = 0; c2 < 32; c2++) {
                    ulonglong2 v = hv[c2];
                    ulonglong2 wA = w2d[c2 * 64 + o];
                    ulonglong2 wB = w2d[c2 * 64 + o2];
                    accA = fma2(wA.x, v.x, accA); accA = fma2(wA.y, v.y, accA);
                    accB = fma2(wB.x, v.x, accB); accB = fma2(wB.y, v.y, accB);
                }
                float* hrow = h2i + (pg * 17 + prow) * 128;
                float a0, a1; f2up(accA, a0, a1);
                a0 = a0 > 0.f ? a0 : 0.01f * a0;
                a1 = a1 > 0.f ? a1 : 0.01f * a1;
                hrow[o * 2]     = a0;
                hrow[o * 2 + 1] = a1;
                f2up(accB, a0, a1);
                a0 = a0 > 0.f ? a0 : 0.01f * a0;
                a1 = a1 > 0.f ? a1 : 0.01f * a1;
                hrow[o2 * 2]     = a0;
                hrow[o2 * 2 + 1] = a1;
            }
        }
    }
    __syncthreads();
    {
        int mi = t >> 7, o = t & 127;
        int pg = mi >> 1, j = mi & 1;
        const ulonglong2* hc2 = (const ulonglong2*)(h2i + pg * 17 * 128);
        float acc = b3[o];
#pragma unroll 4
        for (int c4 = 0; c4 < 16; c4++) {
            float4 w = ((const float4*)g_s2w3p)[c4 * 128 + o];
            ulonglong2 p0 = hc2[2 * c4], p1 = hc2[2 * c4 + 1];
            float l0, h0v, l1, h1v, l2, h2v, l3, h3v;
            f2up(p0.x, l0, h0v); f2up(p0.y, l1, h1v);
            f2up(p1.x, l2, h2v); f2up(p1.y, l3, h3v);
            float v0 = j ? h0v : l0, v1 = j ? h1v : l1;
            float v2 = j ? h2v : l2, v3 = j ? h3v : l3;
            acc += w.x * v0 + w.y * v1 + w.z * v2 + w.w * v3;
        }
        fr2[mi * 128 + o] = acc;
    }
    __syncthreads();
    {
        int ch = t & 255, grp = t >> 8;
        int m0 = grp * 2, m1 = grp * 2 + 1;
        const float4* ap = (const float4*)g_Ap;
        float a0 = 0.f, a1 = 0.f;
        for (int c4 = 0; c4 < 32; c4++) {
            float4 w = ap[c4 * 256 + ch];
            float4 v0 = *(const float4*)(feat + m0 * 17 * 128 + c4 * 4);
            float4 v1 = *(const float4*)(feat + m1 * 17 * 128 + c4 * 4);
            a0 += w.x * v0.x + w.y * v0.y + w.z * v0.z + w.w * v0.w;
            a1 += w.x * v1.x + w.y * v1.y + w.z * v1.z + w.w * v1.w;
        }
        for (int c4 = 0; c4 < 32; c4++) {
            float4 w = ap[(32 + c4) * 256 + ch];
            float4 v0 = *(const float4*)(fr2 + m0 * 128 + c4 * 4);
            float4 v1 = *(const float4*)(fr2 + m1 * 128 + c4 * 4);
            a0 += w.x * v0.x + w.y * v0.y + w.z * v0.z + w.w * v0.w;
            a1 += w.x * v1.x + w.y * v1.y + w.z * v1.z + w.w * v1.w;
        }
        float cv = g_cvec[ch];
        us[m0 * 256 + ch] = a0 + cv;
        us[m1 * 256 + ch] = a1 + cv;
    }
    __syncthreads();
    {
        int mi = t >> 7, rem = t & 127, c = rem >> 1, oh = rem & 1;
        const float* ur = us + mi * 256 + 128 + oh * 64;
        float acc = 0.f;
#pragma unroll 4
        for (int o = 0; o < 64; o++) acc += __ldg(w3 + (oh * 64 + o) * 64 + c) * ur[o];
        zs[(mi * 64 + c) * 2 + oh] = acc;
    }
    __syncthreads();
    for (int task = wid; task < 72; task += 16) {
        float s = 0.f;
        if (task < 64) {
            int mi = task >> 4, j = task & 15;
            const float* uf = us + mi * 256;
            const float* fr = feat + (mi * 17 + 1 + j) * 128;
#pragma unroll
            for (int k = 0; k < 4; k++) { int o = lane + 32 * k; s += uf[o] * fr[o]; }
            const float* hj = h2i + ((mi >> 1) * 17 + 1 + j) * 128;
#pragma unroll
            for (int k = 0; k < 2; k++) {
                int c = lane + 32 * k;
                s += (zs[(mi * 64 + c) * 2] + zs[(mi * 64 + c) * 2 + 1]) * hj[c * 2 + (mi & 1)];
            }
        } else if (task < 68) {
            int mi = task - 64;
            const float* fl = feat + mi * 17 * 128;
            const float* fh = fr2 + mi * 128;
#pragma unroll
            for (int k = 0; k < 4; k++) {
                int o = lane + 32 * k;
                s += __ldg(&g_vb[o]) * fl[o] + __ldg(&g_vb[128 + o]) * fh[o];
            }
        } else {
            int mi = task - 68;
            const float* uh = us + mi * 256 + 128;
#pragma unroll
            for (int k = 0; k < 4; k++) { int o = lane + 32 * k; s += uh[o] * __ldg(b3 + o); }
        }
#pragma unroll
        for (int off = 16; off; off >>= 1) s += __shfl_down_sync(0xffffffffu, s, off);
        if (lane == 0) {
            if (task < 64) lgA[task] = s;
            else if (task < 68) lgB[task - 64] = s;
            else lgC[task - 68] = s;
        }
    }
    __syncthreads();

    if (t < 4) {
        float ex = lgB[t] + lgC[t] + g_s0[0];
        float l[16], mx = -3.4e38f;
#pragma unroll
        for (int j = 0; j < 16; j++) { l[j] = lgA[t * 16 + j] + ex; mx = fmaxf(mx, l[j]); }
        float sum = 0.f;
#pragma unroll
        for (int j = 0; j < 16; j++) { l[j] = expf(l[j] - mx); sum += l[j]; }
        float inv = 1.f / sum;
        float nx = 0.f, ny = 0.f, nz = 0.f;
#pragma unroll
        for (int j = 0; j < 16; j++) {
            float w = l[j] * inv;
            const float* kpp = knnx + (t * 17 + 1 + j) * 3;
            nx += w * kpp[0]; ny += w * kpp[1]; nz += w * kpp[2];
        }
        float* po = out_new + (size_t)(bm0 + t) * 3;
        po[0] = nx; po[1] = ny; po[2] = nz;
    }
}

// ---------------- launch ---------------------------------------------------
extern "C" void kernel_launch(void* const* d_in, const int* in_sizes, int n_in,
                              void* d_out, int out_size) {
    const float* x      = (const float*)d_in[0];
    const float* gf     = (const float*)d_in[1];
    const float* c1_w1  = (const float*)d_in[2];
    const float* c1_b1  = (const float*)d_in[3];
    const float* c1_w2  = (const float*)d_in[4];
    const float* c1_b2  = (const float*)d_in[5];
    const float* cf_w1  = (const float*)d_in[6];
    const float* cf_b1  = (const float*)d_in[7];
    const float* cf_w2  = (const float*)d_in[8];
    const float* cf_b2  = (const float*)d_in[9];
    const float* cs_w1  = (const float*)d_in[10];
    const float* cs_b1  = (const float*)d_in[11];
    const float* cs_w2  = (const float*)d_in[12];
    const float* cs_b2  = (const float*)d_in[13];
    const float* s2_w1  = (const float*)d_in[14];
    const float* s2_b1  = (const float*)d_in[15];
    const float* s2_g1  = (const float*)d_in[16];
    const float* s2_bb1 = (const float*)d_in[17];
    const float* s2_w2  = (const float*)d_in[18];
    const float* s2_b2  = (const float*)d_in[19];
    const float* s2_g2  = (const float*)d_in[20];
    const float* s2_bb2 = (const float*)d_in[21];
    const float* s2_w3  = (const float*)d_in[22];
    const float* s2_b3  = (const float*)d_in[23];
    const float* q_w    = (const float*)d_in[24];
    const float* q_b    = (const float*)d_in[25];
    const float* k_w    = (const float*)d_in[26];
    const float* k_b    = (const float*)d_in[27];
    float* out = (float*)d_out;

    static bool s_init = false;
    static cudaStream_t st;
    static cudaEvent_t evF, evD;
    const int FEAT_SMEM = (384 * FS + 96) * 4;
    const int ATTN_SMEM = 19812 * 4;
    // exact layout size: 3*NP (points SoA) + 8704 (sdl) + 8704 (sil)
    //                    + 4352 (t1d) + 4352 (t1i) = 50688 floats = 202752 B
    const int KNN_SMEM  = (3 * NP + 8704 + 8704 + 4352 + 4352) * 4;
    if (!s_init) {
        cudaStreamCreateWithFlags(&st, cudaStreamNonBlocking);
        cudaEventCreateWithFlags(&evF, cudaEventDisableTiming);
        cudaEventCreateWithFlags(&evD, cudaEventDisableTiming);
        cudaFuncSetAttribute(k_feat, cudaFuncAttributeMaxDynamicSharedMemorySize, FEAT_SMEM);
        cudaFuncSetAttribute(k_knn,  cudaFuncAttributeMaxDynamicSharedMemorySize, KNN_SMEM);
        cudaFuncSetAttribute(k_fps,  cudaFuncAttributeMaxDynamicSharedMemorySize, NP * 3 * 4);
        cudaFuncSetAttribute(k_attn, cudaFuncAttributeMaxDynamicSharedMemorySize, ATTN_SMEM);
        s_init = true;
    }

    cudaEventRecord(evF, 0);
    cudaStreamWaitEvent(st, evF, 0);
    k_fps<<<BN, 512, NP * 3 * 4, st>>>(x, out);                       // #1
    k_prep<<<730, 256>>>(cs_w1, cs_w2, c1_w2,                         // #2
                         s2_w1, s2_b1, s2_g1, s2_bb1,
                         s2_w2, s2_b2, s2_g2, s2_bb2, s2_w3,
                         q_w, k_w, q_b, k_b,
                         gf, cf_w1, cf_b1, cf_w2, cf_b2);
    k_prep2<<<BN, 256>>>(cs_b1);                                      // #3
    k_knn<<<(BN * MP) / 64, 512, KNN_SMEM, st>>>(x);                  // #4 <- profiled
    k_feat<<<(BN * NP) / 32, 256, FEAT_SMEM>>>(x,                     // #5
        c1_w1, c1_b1, c1_b2, cs_b2);
    cudaEventRecord(evD, st);
    cudaStreamWaitEvent(0, evD, 0);
    k_attn<<<(BN * MP) / 4, 512, ATTN_SMEM>>>(x, s2_w3, s2_b3,        // #6
        out + (size_t)BN * MP * 3);
}